// round 15
// baseline (speedup 1.0000x reference)
#include <cuda_runtime.h>
#include <cuda_fp16.h>
#include <math.h>
#include <stdint.h>

#define HIDDEN 1536
#define NHEADS 12
#define HDIM 128
#define MLPH 6144
#define TXT 256
#define LX 4352
#define NC 20
#define LC 4116
#define NROWS 4372          // LX + NC
#define W1OUT 10752         // 3*HIDDEN + MLPH
#define QKVW 4608           // 3*HIDDEN
#define CCW 7680            // HIDDEN + MLPH

typedef __half f16;

// ---------------- scratch (static device globals; no runtime allocation) ---
static __device__ float g_mod[3 * HIDDEN];
static __device__ f16   g_xmh[(size_t)NROWS * HIDDEN];
static __device__ f16   g_w1h[(size_t)W1OUT * HIDDEN];
static __device__ f16   g_w2h[(size_t)HIDDEN * CCW];
static __device__ float g_h[(size_t)NROWS * QKVW];
static __device__ f16   g_q1h[(size_t)NHEADS * LX * HDIM];
static __device__ f16   g_k1h[(size_t)NHEADS * LX * HDIM];
static __device__ f16   g_v1h[(size_t)NHEADS * LX * HDIM];
static __device__ float g_q2[(size_t)NHEADS * NC * HDIM];
static __device__ float g_k2[(size_t)NHEADS * LC * HDIM];
static __device__ float g_v2[(size_t)NHEADS * LC * HDIM];
static __device__ float g_s2[(size_t)NHEADS * NC * LC];
static __device__ float g_o2[(size_t)NHEADS * NC * HDIM];
static __device__ f16   g_cch[(size_t)NROWS * CCW];
static __device__ float g_out[(size_t)2 * NROWS * HIDDEN];   // GEMM2 K-parts

// ---------------- reductions ----------------------------------------------
__device__ __forceinline__ float warp_sum(float v) {
    #pragma unroll
    for (int o = 16; o > 0; o >>= 1) v += __shfl_xor_sync(0xffffffffu, v, o);
    return v;
}
__device__ __forceinline__ float warp_max(float v) {
    #pragma unroll
    for (int o = 16; o > 0; o >>= 1) v = fmaxf(v, __shfl_xor_sync(0xffffffffu, v, o));
    return v;
}
template <int NT>
__device__ __forceinline__ float block_sum(float v, float* sbuf) {
    v = warp_sum(v);
    int lane = threadIdx.x & 31, w = threadIdx.x >> 5;
    if (lane == 0) sbuf[w] = v;
    __syncthreads();
    if (threadIdx.x < 32) {
        float x = (threadIdx.x < NT / 32) ? sbuf[threadIdx.x] : 0.f;
        x = warp_sum(x);
        if (threadIdx.x == 0) sbuf[0] = x;
    }
    __syncthreads();
    float r = sbuf[0];
    __syncthreads();
    return r;
}
template <int NT>
__device__ __forceinline__ float block_max(float v, float* sbuf) {
    v = warp_max(v);
    int lane = threadIdx.x & 31, w = threadIdx.x >> 5;
    if (lane == 0) sbuf[w] = v;
    __syncthreads();
    if (threadIdx.x < 32) {
        float x = (threadIdx.x < NT / 32) ? sbuf[threadIdx.x] : -1e30f;
        x = warp_max(x);
        if (threadIdx.x == 0) sbuf[0] = x;
    }
    __syncthreads();
    float r = sbuf[0];
    __syncthreads();
    return r;
}

// ---------------- helpers ---------------------------------------------------
__device__ __forceinline__ uint32_t pack2h(float x, float y) {
    __half2 h = __halves2half2(__float2half_rn(x), __float2half_rn(y));
    return *reinterpret_cast<uint32_t*>(&h);
}
__device__ __forceinline__ float gelu_f(float xv) {
    float inner = 0.7978845608028654f * fmaf(0.044715f * xv * xv, xv, xv);
    return 0.5f * xv * (1.f + tanhf(inner));
}

// ======================= HMMA helpers ======================================
__device__ __forceinline__ uint32_t smem_u32(const void* p) {
    uint32_t a;
    asm("{ .reg .u64 t; cvta.to.shared.u64 t, %1; cvt.u32.u64 %0, t; }"
        : "=r"(a) : "l"(p));
    return a;
}
__device__ __forceinline__ void ldsm4(uint32_t* r, uint32_t addr) {
    asm volatile("ldmatrix.sync.aligned.m8n8.x4.shared.b16 {%0,%1,%2,%3}, [%4];"
                 : "=r"(r[0]), "=r"(r[1]), "=r"(r[2]), "=r"(r[3]) : "r"(addr));
}
__device__ __forceinline__ void ldsm4t(uint32_t* r, uint32_t addr) {
    asm volatile("ldmatrix.sync.aligned.m8n8.x4.trans.shared.b16 {%0,%1,%2,%3}, [%4];"
                 : "=r"(r[0]), "=r"(r[1]), "=r"(r[2]), "=r"(r[3]) : "r"(addr));
}
__device__ __forceinline__ void mma_f16(float* c, const uint32_t* a,
                                        uint32_t b0, uint32_t b1) {
    asm volatile(
        "mma.sync.aligned.m16n8k16.row.col.f32.f16.f16.f32 "
        "{%0,%1,%2,%3}, {%4,%5,%6,%7}, {%8,%9}, {%0,%1,%2,%3};"
        : "+f"(c[0]), "+f"(c[1]), "+f"(c[2]), "+f"(c[3])
        : "r"(a[0]), "r"(a[1]), "r"(a[2]), "r"(a[3]), "r"(b0), "r"(b1));
}
__device__ __forceinline__ void cp_async16(uint32_t dst, const void* src, int sz) {
    asm volatile("cp.async.cg.shared.global [%0], [%1], 16, %2;"
                 :: "r"(dst), "l"(src), "r"(sz) : "memory");
}
__device__ __forceinline__ void cp_commit() {
    asm volatile("cp.async.commit_group;" ::: "memory");
}
__device__ __forceinline__ void cp_wait1() {
    asm volatile("cp.async.wait_group 1;" ::: "memory");
}
__device__ __forceinline__ void cp_wait2() {
    asm volatile("cp.async.wait_group 2;" ::: "memory");
}

// smem: per stage 2 tiles (A, B): 128 rows x 32 f16, row stride 80 B
#define SPB      80
#define T_BYTES  (128 * SPB)          // 10240
#define STAGE_B  (2 * T_BYTES)        // 20480
#define NSTAGE   4
#define HG_SMEM  (NSTAGE * STAGE_B)   // 81920 -> 2 CTAs/SM

// ======== fp16 GEMM: C = A@B^T + bias ======================================
__global__ void __launch_bounds__(256, 2) gemm_f16(
    const f16* __restrict__ Ah, int lda,
    const f16* __restrict__ Bh, int ldb,
    float* __restrict__ C, int ldc,
    f16* __restrict__ Gh, int gelu_n0,
    int M, int N, int K, const float* __restrict__ bias)
{
    extern __shared__ char smem[];
    uint32_t sbase = smem_u32(smem);
    int tid = threadIdx.x, wid = tid >> 5, lane = tid & 31;

    const int GRP = 8;
    int npn = gridDim.x, npm = gridDim.y;
    int pid = blockIdx.y * npn + blockIdx.x;
    int gsz = GRP * npn;
    int gid = pid / gsz;
    int fm = gid * GRP;
    int gm = min(GRP, npm - fm);
    int pid_m = fm + (pid % gsz) % gm;
    int pid_n = (pid % gsz) / gm;
    int m0 = pid_m * 128, n0 = pid_n * 128;

    int warp_m = wid & 3;
    int warp_n = wid >> 2;
    int lrow = lane & 15, lhalf = lane >> 4;

    uint32_t a_off[2], b_off[4];
    #pragma unroll
    for (int i = 0; i < 2; ++i)
        a_off[i] = (uint32_t)((warp_m * 32 + i * 16 + lrow) * SPB + lhalf * 16);
    #pragma unroll
    for (int g = 0; g < 4; ++g)
        b_off[g] = (uint32_t)((warp_n * 64 + g * 16 + lrow) * SPB + lhalf * 16);

    float acc[2][8][4];
    #pragma unroll
    for (int i = 0; i < 2; ++i)
        #pragma unroll
        for (int j = 0; j < 8; ++j)
            #pragma unroll
            for (int t = 0; t < 4; ++t) acc[i][j][t] = 0.f;

    int nch = K >> 5;

    auto issue = [&](int c) {
        if (c < nch) {
            int kc = c << 5;
            uint32_t sb = sbase + (uint32_t)(c % NSTAGE) * STAGE_B;
            #pragma unroll
            for (int u4 = 0; u4 < 4; ++u4) {
                int u = tid + 256 * u4;
                int tile = u >> 9;              // 0=A, 1=B
                int r = (u >> 2) & 127;
                int c16 = u & 3;
                uint32_t dst = sb + (uint32_t)(tile * T_BYTES + r * SPB + c16 * 16);
                if (tile == 0) {
                    int sz = (m0 + r < M) ? 16 : 0;
                    cp_async16(dst, Ah + (size_t)(m0 + r) * lda + kc + c16 * 8, sz);
                } else {
                    cp_async16(dst, Bh + (size_t)(n0 + r) * ldb + kc + c16 * 8, 16);
                }
            }
        }
        cp_commit();
    };

    issue(0); issue(1); issue(2);

    for (int c = 0; c < nch; ++c) {
        cp_wait2();
        __syncthreads();
        issue(c + 3);
        uint32_t sb = sbase + (uint32_t)(c % NSTAGE) * STAGE_B;
        #pragma unroll
        for (int k16 = 0; k16 < 2; ++k16) {
            uint32_t koff = (uint32_t)(k16 * 32);
            uint32_t ah[2][4], bh[4][4];
            #pragma unroll
            for (int i = 0; i < 2; ++i)
                ldsm4(ah[i], sb + 0 * T_BYTES + a_off[i] + koff);
            #pragma unroll
            for (int g = 0; g < 4; ++g)
                ldsm4(bh[g], sb + 1 * T_BYTES + b_off[g] + koff);
            #pragma unroll
            for (int i = 0; i < 2; ++i)
                #pragma unroll
                for (int j = 0; j < 8; ++j) {
                    int g = j >> 1, sI = j & 1;
                    mma_f16(acc[i][j], ah[i], bh[g][sI], bh[g][sI + 2]);
                }
        }
    }

    int trow = lane >> 2, tc2 = (lane & 3) * 2;
    #pragma unroll
    for (int i = 0; i < 2; ++i) {
        #pragma unroll
        for (int half = 0; half < 2; ++half) {
            int m = m0 + warp_m * 32 + i * 16 + half * 8 + trow;
            if (m >= M) continue;
            #pragma unroll
            for (int j = 0; j < 8; ++j) {
                int n = n0 + warp_n * 64 + j * 8 + tc2;
                float vx = acc[i][j][half * 2 + 0];
                float vy = acc[i][j][half * 2 + 1];
                if (bias) { vx += bias[n]; vy += bias[n + 1]; }
                if (n >= gelu_n0) {
                    vx = gelu_f(vx); vy = gelu_f(vy);
                    int cc = HIDDEN + n - gelu_n0;
                    *reinterpret_cast<uint32_t*>(Gh + (size_t)m * CCW + cc) =
                        pack2h(vx, vy);
                } else {
                    *reinterpret_cast<float2*>(C + (size_t)m * ldc + n) =
                        make_float2(vx, vy);
                }
            }
        }
    }
}

// ================= flash attention for block 1 =============================
#define BK 64
#define FSTR 272                       // 128*2 + 16 pad
#define FQ_PLANE (128 * FSTR)          // 34816
#define FK_PLANE (BK * FSTR)           // 17408
#define FS_OFF   FQ_PLANE              // 34816
#define FSTAGE   (2 * FK_PLANE)        // 34816 (K + V)
#define FNS      3
#define FLASH_SMEM (FS_OFF + FNS * FSTAGE)  // 139264
#define NKT (LX / BK)                  // 68

__global__ void __launch_bounds__(256, 1) flash1(
    const f16* __restrict__ Qh,
    const f16* __restrict__ Kh, const f16* __restrict__ Vh,
    f16* __restrict__ Och)
{
    extern __shared__ char smem[];
    uint32_t sbase = smem_u32(smem);
    int tid = threadIdx.x, wid = tid >> 5, lane = tid & 31;
    int head = blockIdx.y;
    int q0 = blockIdx.x * 128;
    size_t hb = (size_t)head * LX * HDIM;
    const f16* qp0 = Qh + hb + (size_t)q0 * HDIM;
    const f16* kp[2] = { Kh + hb, Vh + hb };

    #pragma unroll
    for (int u8 = 0; u8 < 8; ++u8) {
        int u = tid + 256 * u8;
        int r = (u >> 4) & 127, c = u & 15;
        cp_async16(sbase + (uint32_t)(r * FSTR + c * 16),
                   qp0 + (size_t)r * HDIM + c * 8, 16);
    }
    cp_commit();

    auto issueKV = [&](int it) {
        if (it < NKT) {
            int kv0 = it * BK;
            #pragma unroll
            for (int u8 = 0; u8 < 8; ++u8) {
                int u = tid + 256 * u8;
                int pl = u >> 10, r = (u >> 4) & 63, c = u & 15;
                cp_async16(sbase + (uint32_t)(FS_OFF + (it % FNS) * FSTAGE +
                                              pl * FK_PLANE + r * FSTR + c * 16),
                           kp[pl] + (size_t)(kv0 + r) * HDIM + c * 8, 16);
            }
        }
        cp_commit();
    };
    issueKV(0);
    issueKV(1);

    uint32_t a_addr = sbase + (uint32_t)((wid * 16 + (lane & 15)) * FSTR +
                                         (lane >> 4) * 16);
    uint32_t bk_rel = (uint32_t)((lane & 15) * FSTR + (lane >> 4) * 16);
    uint32_t bv_rel = (uint32_t)(((((lane >> 3) & 1) * 8) + (lane & 7)) * FSTR +
                                 ((lane >> 4) & 1) * 16);

    float accO[16][4];
    #pragma unroll
    for (int j = 0; j < 16; ++j)
        #pragma unroll
        for (int t = 0; t < 4; ++t) accO[j][t] = 0.f;
    float mrow0 = -1e30f, mrow1 = -1e30f, lsum0 = 0.f, lsum1 = 0.f;
    const float scl = 0.08838834764831845f;

    for (int it = 0; it < NKT; ++it) {
        cp_wait1();
        __syncthreads();
        issueKV(it + 2);
        uint32_t kb = sbase + FS_OFF + (uint32_t)(it % FNS) * FSTAGE;

        float s[8][4];
        #pragma unroll
        for (int j = 0; j < 8; ++j)
            #pragma unroll
            for (int t = 0; t < 4; ++t) s[j][t] = 0.f;
        #pragma unroll
        for (int ks = 0; ks < 8; ++ks) {
            uint32_t aqh[4];
            ldsm4(aqh, a_addr + ks * 32);
            uint32_t bh[4][4];
            #pragma unroll
            for (int g = 0; g < 4; ++g)
                ldsm4(bh[g], kb + bk_rel + g * (16 * FSTR) + ks * 32);
            #pragma unroll
            for (int j = 0; j < 8; ++j)
                mma_f16(s[j], aqh, bh[j >> 1][j & 1], bh[j >> 1][(j & 1) + 2]);
        }

        float m0 = -1e30f, m1 = -1e30f;
        #pragma unroll
        for (int j = 0; j < 8; ++j) {
            s[j][0] *= scl; s[j][1] *= scl; s[j][2] *= scl; s[j][3] *= scl;
            m0 = fmaxf(m0, fmaxf(s[j][0], s[j][1]));
            m1 = fmaxf(m1, fmaxf(s[j][2], s[j][3]));
        }
        m0 = fmaxf(m0, __shfl_xor_sync(0xffffffffu, m0, 1));
        m0 = fmaxf(m0, __shfl_xor_sync(0xffffffffu, m0, 2));
        m1 = fmaxf(m1, __shfl_xor_sync(0xffffffffu, m1, 1));
        m1 = fmaxf(m1, __shfl_xor_sync(0xffffffffu, m1, 2));
        float mn0 = fmaxf(mrow0, m0), mn1 = fmaxf(mrow1, m1);
        float al0 = __expf(mrow0 - mn0), al1 = __expf(mrow1 - mn1);
        mrow0 = mn0; mrow1 = mn1;

        uint32_t ph[8][2];
        float ps0 = 0.f, ps1 = 0.f;
        #pragma unroll
        for (int j = 0; j < 8; ++j) {
            float p00 = __expf(s[j][0] - mn0), p01 = __expf(s[j][1] - mn0);
            float p10 = __expf(s[j][2] - mn1), p11 = __expf(s[j][3] - mn1);
            ps0 += p00 + p01; ps1 += p10 + p11;
            ph[j][0] = pack2h(p00, p01);
            ph[j][1] = pack2h(p10, p11);
        }
        lsum0 = lsum0 * al0 + ps0;
        lsum1 = lsum1 * al1 + ps1;
        #pragma unroll
        for (int j = 0; j < 16; ++j) {
            accO[j][0] *= al0; accO[j][1] *= al0;
            accO[j][2] *= al1; accO[j][3] *= al1;
        }

        uint32_t vb = kb + FK_PLANE;
        #pragma unroll
        for (int s4 = 0; s4 < 4; ++s4) {
            uint32_t Ahf[4] = { ph[2 * s4][0], ph[2 * s4][1],
                                ph[2 * s4 + 1][0], ph[2 * s4 + 1][1] };
            #pragma unroll
            for (int g = 0; g < 8; ++g) {
                uint32_t bvh[4];
                ldsm4t(bvh, vb + bv_rel + s4 * (16 * FSTR) + g * 32);
                mma_f16(accO[2 * g],     Ahf, bvh[0], bvh[1]);
                mma_f16(accO[2 * g + 1], Ahf, bvh[2], bvh[3]);
            }
        }
    }

    lsum0 += __shfl_xor_sync(0xffffffffu, lsum0, 1);
    lsum0 += __shfl_xor_sync(0xffffffffu, lsum0, 2);
    lsum1 += __shfl_xor_sync(0xffffffffu, lsum1, 1);
    lsum1 += __shfl_xor_sync(0xffffffffu, lsum1, 2);
    float inv0 = 1.f / lsum0, inv1 = 1.f / lsum1;
    int r0 = q0 + wid * 16 + (lane >> 2);
    int cbase = head * HDIM + (lane & 3) * 2;
    #pragma unroll
    for (int j = 0; j < 16; ++j) {
        int c = cbase + j * 8;
        *reinterpret_cast<uint32_t*>(Och + (size_t)r0 * CCW + c) =
            pack2h(accO[j][0] * inv0, accO[j][1] * inv0);
        *reinterpret_cast<uint32_t*>(Och + (size_t)(r0 + 8) * CCW + c) =
            pack2h(accO[j][2] * inv1, accO[j][3] * inv1);
    }
}

// ---------------- SIMT GEMM (block-2 QK^T only) ----------------------------
__global__ void __launch_bounds__(256) sgemm_abt(
    const float* __restrict__ A, int lda, long long sA,
    const float* __restrict__ B, int ldb, long long sB,
    float* __restrict__ C, int ldc, long long sC,
    int M, int N, int K, float alpha)
{
    __shared__ float As[8][128];
    __shared__ float Bs[8][128];
    int bz = blockIdx.z;
    A += (size_t)sA * bz;
    B += (size_t)sB * bz;
    C += (size_t)sC * bz;
    int m0 = blockIdx.y * 128;
    int n0 = blockIdx.x * 128;
    int tid = threadIdx.x;
    int tx = tid & 15, ty = tid >> 4;
    int lrow = tid >> 1;
    int lcol = (tid & 1) * 4;

    float acc[8][8];
    #pragma unroll
    for (int i = 0; i < 8; i++)
        #pragma unroll
        for (int j = 0; j < 8; j++) acc[i][j] = 0.f;

    for (int k0 = 0; k0 < K; k0 += 8) {
        float4 av = make_float4(0.f, 0.f, 0.f, 0.f);
        float4 bv = make_float4(0.f, 0.f, 0.f, 0.f);
        if (m0 + lrow < M && k0 + lcol < K)
            av = *reinterpret_cast<const float4*>(A + (size_t)(m0 + lrow) * lda + k0 + lcol);
        if (n0 + lrow < N && k0 + lcol < K)
            bv = *reinterpret_cast<const float4*>(B + (size_t)(n0 + lrow) * ldb + k0 + lcol);
        As[lcol + 0][lrow] = av.x; As[lcol + 1][lrow] = av.y;
        As[lcol + 2][lrow] = av.z; As[lcol + 3][lrow] = av.w;
        Bs[lcol + 0][lrow] = bv.x; Bs[lcol + 1][lrow] = bv.y;
        Bs[lcol + 2][lrow] = bv.z; Bs[lcol + 3][lrow] = bv.w;
        __syncthreads();
        #pragma unroll
        for (int k = 0; k < 8; k++) {
            float ra[8], rb[8];
            #pragma unroll
            for (int i = 0; i < 8; i++) ra[i] = As[k][ty + 16 * i];
            #pragma unroll
            for (int j = 0; j < 8; j++) rb[j] = Bs[k][tx + 16 * j];
            #pragma unroll
            for (int i = 0; i < 8; i++)
                #pragma unroll
                for (int j = 0; j < 8; j++)
                    acc[i][j] = fmaf(ra[i], rb[j], acc[i][j]);
        }
        __syncthreads();
    }

    #pragma unroll
    for (int i = 0; i < 8; i++) {
        int m = m0 + ty + 16 * i;
        if (m >= M) continue;
        #pragma unroll
        for (int j = 0; j < 8; j++) {
            int n = n0 + tx + 16 * j;
            if (n >= N) continue;
            C[(size_t)m * ldc + n] = alpha * acc[i][j];
        }
    }
}

// ---------------- block-2 PV: split-K rank-1 updates -----------------------
#define KSPLIT 16
__global__ void __launch_bounds__(256) zero_o2()
{
    int idx = blockIdx.x * 256 + threadIdx.x;
    if (idx < NHEADS * NC * HDIM) g_o2[idx] = 0.f;
}
__global__ void __launch_bounds__(256) pv2_kernel()
{
    int h = blockIdx.y, ks = blockIdx.x;
    int chunk = (LC + KSPLIT - 1) / KSPLIT;
    int k0 = ks * chunk, k1 = min(LC, k0 + chunk);
    int d = threadIdx.x & 127, g = threadIdx.x >> 7;
    const float* S = g_s2 + (size_t)h * NC * LC;
    const float* V = g_v2 + (size_t)h * LC * HDIM;
    float acc[10];
    #pragma unroll
    for (int i = 0; i < 10; ++i) acc[i] = 0.f;
    for (int k = k0; k < k1; ++k) {
        float v = V[(size_t)k * HDIM + d];
        #pragma unroll
        for (int i = 0; i < 10; ++i)
            acc[i] = fmaf(__ldg(S + (size_t)(g * 10 + i) * LC + k), v, acc[i]);
    }
    #pragma unroll
    for (int i = 0; i < 10; ++i)
        atomicAdd(&g_o2[((size_t)h * NC + g * 10 + i) * HDIM + d], acc[i]);
}
__global__ void __launch_bounds__(256) o2_to_cc()
{
    int idx = blockIdx.x * 256 + threadIdx.x;
    if (idx >= NHEADS * NC * HDIM) return;
    int d = idx & 127;
    int i = (idx >> 7) % NC;
    int h = idx / (NC * HDIM);
    g_cch[(size_t)(LX + i) * CCW + h * HDIM + d] = __float2half_rn(g_o2[idx]);
}

// ---------------- convert fp32 -> fp16 -------------------------------------
__global__ void __launch_bounds__(256) convert_h(
    const float4* __restrict__ src, uint2* __restrict__ h, int n4)
{
    int idx = blockIdx.x * 256 + threadIdx.x;
    if (idx >= n4) return;
    float4 v = src[idx];
    uint2 r;
    r.x = pack2h(v.x, v.y);
    r.y = pack2h(v.z, v.w);
    h[idx] = r;
}

// ---------------- modulation: m = silu(vec) @ mod_w^T + mod_b --------------
__global__ void __launch_bounds__(256) mod_kernel(
    const float* __restrict__ vec, const float* __restrict__ mod_w,
    const float* __restrict__ mod_b)
{
    __shared__ float sv[HIDDEN];
    for (int i = threadIdx.x; i < HIDDEN; i += 256) {
        float xv = vec[i];
        sv[i] = xv / (1.f + __expf(-xv));
    }
    __syncthreads();
    int n = blockIdx.x * 8 + (threadIdx.x >> 5);
    int lane = threadIdx.x & 31;
    const float4* w4 = reinterpret_cast<const float4*>(mod_w + (size_t)n * HIDDEN);
    float acc = 0.f;
    #pragma unroll
    for (int i = 0; i < 12; ++i) {
        float4 w = w4[lane + 32 * i];
        int k = (lane + 32 * i) * 4;
        acc += w.x * sv[k] + w.y * sv[k + 1] + w.z * sv[k + 2] + w.w * sv[k + 3];
    }
    acc = warp_sum(acc);
    if (lane == 0) g_mod[n] = acc + mod_b[n];
}

// ---------------- layernorm + modulate -> fp16 (float4) ---------------------
__global__ void __launch_bounds__(128) ln_mod_kernel(
    const float* __restrict__ x, const float* __restrict__ concepts)
{
    __shared__ float sbuf[4];
    int row = blockIdx.x;
    const float4* src = (row < LX)
        ? reinterpret_cast<const float4*>(x + (size_t)row * HIDDEN)
        : reinterpret_cast<const float4*>(concepts + (size_t)(row - LX) * HIDDEN);
    int tid = threadIdx.x;
    float4 v[3];
    float s = 0.f;
    #pragma unroll
    for (int i = 0; i < 3; i++) {
        v[i] = src[tid + 128 * i];
        s += v[i].x + v[i].y + v[i].z + v[i].w;
    }
    s = block_sum<128>(s, sbuf);
    float mu = s * (1.0f / 1536.0f);
    float s2 = 0.f;
    #pragma unroll
    for (int i = 0; i < 3; i++) {
        float dx = v[i].x - mu, dy = v[i].y - mu, dz = v[i].z - mu, dw = v[i].w - mu;
        s2 = fmaf(dx, dx, s2); s2 = fmaf(dy, dy, s2);
        s2 = fmaf(dz, dz, s2); s2 = fmaf(dw, dw, s2);
    }
    s2 = block_sum<128>(s2, sbuf);
    float rstd = rsqrtf(s2 * (1.0f / 1536.0f) + 1e-6f);
    #pragma unroll
    for (int i = 0; i < 3; i++) {
        int j4 = tid + 128 * i;
        float4 sc = *reinterpret_cast<const float4*>(g_mod + HIDDEN + j4 * 4);
        float4 sh = *reinterpret_cast<const float4*>(g_mod + j4 * 4);
        float ox = (1.f + sc.x) * ((v[i].x - mu) * rstd) + sh.x;
        float oy = (1.f + sc.y) * ((v[i].y - mu) * rstd) + sh.y;
        float oz = (1.f + sc.z) * ((v[i].z - mu) * rstd) + sh.z;
        float ow = (1.f + sc.w) * ((v[i].w - mu) * rstd) + sh.w;
        uint2 r;
        r.x = pack2h(ox, oy);
        r.y = pack2h(oz, ow);
        *reinterpret_cast<uint2*>(g_xmh + (size_t)row * HIDDEN + j4 * 4) = r;
    }
}

// ---------------- attention prep (warp per token-head, float4) -------------
__device__ __forceinline__ float4 rope4(float4 t, const float* __restrict__ pe,
                                        int tok, int lane)
{
    float4 p0 = *reinterpret_cast<const float4*>(pe + ((size_t)tok * 64 + lane * 2) * 4);
    float4 p1 = *reinterpret_cast<const float4*>(pe + ((size_t)tok * 64 + lane * 2 + 1) * 4);
    float4 r;
    r.x = p0.x * t.x + p0.y * t.y;
    r.y = p0.z * t.x + p0.w * t.y;
    r.z = p1.x * t.z + p1.y * t.w;
    r.w = p1.z * t.z + p1.w * t.w;
    return r;
}

__global__ void __launch_bounds__(384) attn_prep1(
    const float* __restrict__ pe, const float* __restrict__ cpe,
    const float* __restrict__ q_scale, const float* __restrict__ k_scale)
{
    int t = blockIdx.x;
    int h = threadIdx.x >> 5, lane = threadIdx.x & 31;
    const float* hrow = g_h + (size_t)t * QKVW;
    float4 q = *reinterpret_cast<const float4*>(hrow + h * HDIM + lane * 4);
    float4 k = *reinterpret_cast<const float4*>(hrow + HIDDEN + h * HDIM + lane * 4);
    float4 v = *reinterpret_cast<const float4*>(hrow + 2 * HIDDEN + h * HDIM + lane * 4);
    float sq = q.x * q.x + q.y * q.y + q.z * q.z + q.w * q.w;
    float sk = k.x * k.x + k.y * k.y + k.z * k.z + k.w * k.w;
    sq = warp_sum(sq); sk = warp_sum(sk);
    float rq = rsqrtf(sq * (1.f / 128.f) + 1e-6f);
    float rk = rsqrtf(sk * (1.f / 128.f) + 1e-6f);
    float4 qs = *reinterpret_cast<const float4*>(q_scale + lane * 4);
    float4 ks = *reinterpret_cast<const float4*>(k_scale + lane * 4);
    float4 qn = make_float4(q.x * rq * qs.x, q.y * rq * qs.y,
                            q.z * rq * qs.z, q.w * rq * qs.w);
    float4 kn = make_float4(k.x * rk * ks.x, k.y * rk * ks.y,
                            k.z * rk * ks.z, k.w * rk * ks.w);
    float4 qr = rope4(qn, pe, t, lane);
    float4 kr = rope4(kn, pe, t, lane);
    size_t qi = ((size_t)h * LX + t) * HDIM + lane * 4;
    uint2 r;
    r.x = pack2h(qr.x, qr.y); r.y = pack2h(qr.z, qr.w);
    *reinterpret_cast<uint2*>(g_q1h + qi) = r;
    r.x = pack2h(kr.x, kr.y); r.y = pack2h(kr.z, kr.w);
    *reinterpret_cast<uint2*>(g_k1h + qi) = r;
    r.x = pack2h(v.x, v.y); r.y = pack2h(v.z, v.w);
    *reinterpret_cast<uint2*>(g_v1h + qi) = r;
    if (t >= TXT) {
        int j = NC + (t - TXT);
        float4 kc = rope4(kn, cpe, j, lane);
        size_t ki = ((size_t)h * LC + j) * HDIM + lane * 4;
        *reinterpret_cast<float4*>(g_k2 + ki) = kc;
        *reinterpret_cast<float4*>(g_v2 + ki) = v;
    }
}

__global__ void __launch_bounds__(384) attn_prep2(
    const float* __restrict__ cpe,
    const float* __restrict__ q_scale, const float* __restrict__ k_scale)
{
    int i = blockIdx.x;
    int h = threadIdx.x >> 5, lane = threadIdx.x & 31;
    const float* hrow = g_h + (size_t)(LX + i) * QKVW;
    float4 q = *reinterpret_cast<const float4*>(hrow + h * HDIM + lane * 4);
    float4 k = *reinterpret_cast<const float4*>(hrow + HIDDEN + h * HDIM + lane * 4);
    float4 v = *reinterpret_cast<const float4*>(hrow + 2 * HIDDEN + h * HDIM + lane * 4);
    float sq = q.x * q.x + q.y * q.y + q.z * q.z + q.w * q.w;
    float sk = k.x * k.x + k.y * k.y + k.z * k.z + k.w * k.w;
    sq = warp_sum(sq); sk = warp_sum(sk);
    float rq = rsqrtf(sq * (1.f / 128.f) + 1e-6f);
    float rk = rsqrtf(sk * (1.f / 128.f) + 1e-6f);
    float4 qs = *reinterpret_cast<const float4*>(q_scale + lane * 4);
    float4 ks = *reinterpret_cast<const float4*>(k_scale + lane * 4);
    float4 qn = make_float4(q.x * rq * qs.x, q.y * rq * qs.y,
                            q.z * rq * qs.z, q.w * rq * qs.w);
    float4 kn = make_float4(k.x * rk * ks.x, k.y * rk * ks.y,
                            k.z * rk * ks.z, k.w * rk * ks.w);
    float4 qr = rope4(qn, cpe, i, lane);
    float4 kr = rope4(kn, cpe, i, lane);
    *reinterpret_cast<float4*>(g_q2 + ((size_t)h * NC + i) * HDIM + lane * 4) = qr;
    size_t ki = ((size_t)h * LC + i) * HDIM + lane * 4;
    *reinterpret_cast<float4*>(g_k2 + ki) = kr;
    *reinterpret_cast<float4*>(g_v2 + ki) = v;
}

// ---------------- row softmax (block-2 path) -------------------------------
__global__ void __launch_bounds__(256) softmax_rows(float* __restrict__ S, int ncol)
{
    __shared__ float sbuf[8];
    float* row = S + (size_t)blockIdx.x * ncol;
    int tid = threadIdx.x;
    float v[17];
    float mx = -1e30f;
    #pragma unroll
    for (int i = 0; i < 17; i++) {
        int c = tid + 256 * i;
        v[i] = (c < ncol) ? row[c] : -1e30f;
        mx = fmaxf(mx, v[i]);
    }
    mx = block_max<256>(mx, sbuf);
    float s = 0.f;
    #pragma unroll
    for (int i = 0; i < 17; i++) { v[i] = __expf(v[i] - mx); s += v[i]; }
    s = block_sum<256>(s, sbuf);
    float inv = 1.f / s;
    #pragma unroll
    for (int i = 0; i < 17; i++) {
        int c = tid + 256 * i;
        if (c < ncol) row[c] = v[i] * inv;
    }
}

// ---------------- residual: out = base + gate*(p0 + p1 + b2) (float4) ------
__global__ void __launch_bounds__(256) final_kernel(
    const float* __restrict__ x, const float* __restrict__ concepts,
    const float* __restrict__ b2, float* __restrict__ out)
{
    int idx = blockIdx.x * 256 + threadIdx.x;      // float4 index
    if (idx >= NROWS * (HIDDEN / 4)) return;
    int c4 = idx % (HIDDEN / 4);
    int r = idx / (HIDDEN / 4);
    float4 base = (r < LX)
        ? reinterpret_cast<const float4*>(x)[idx]
        : reinterpret_cast<const float4*>(concepts)[idx - LX * (HIDDEN / 4)];
    float4 g = *reinterpret_cast<const float4*>(g_mod + 2 * HIDDEN + c4 * 4);
    float4 bb = reinterpret_cast<const float4*>(b2)[c4];
    float4 p0 = reinterpret_cast<const float4*>(g_out)[idx];
    float4 p1 = reinterpret_cast<const float4*>(g_out)[idx + NROWS * (HIDDEN / 4)];
    float4 rv;
    rv.x = fmaf(g.x, p0.x + p1.x + bb.x, base.x);
    rv.y = fmaf(g.y, p0.y + p1.y + bb.y, base.y);
    rv.z = fmaf(g.z, p0.z + p1.z + bb.z, base.z);
    rv.w = fmaf(g.w, p0.w + p1.w + bb.w, base.w);
    reinterpret_cast<float4*>(out)[idx] = rv;
}

// ---------------------------------------------------------------------------
extern "C" void kernel_launch(void* const* d_in, const int* in_sizes, int n_in,
                              void* d_out, int out_size)
{
    const float* x        = (const float*)d_in[0];
    const float* concepts = (const float*)d_in[1];
    const float* vec      = (const float*)d_in[2];
    const float* pe       = (const float*)d_in[3];
    const float* cpe      = (const float*)d_in[4];
    const float* w1       = (const float*)d_in[5];
    const float* b1       = (const float*)d_in[6];
    const float* w2       = (const float*)d_in[7];
    const float* b2       = (const float*)d_in[8];
    const float* q_scale  = (const float*)d_in[9];
    const float* k_scale  = (const float*)d_in[10];
    const float* mod_w    = (const float*)d_in[11];
    const float* mod_b    = (const float*)d_in[12];
    float* out = (float*)d_out;

    void* p;
    cudaGetSymbolAddress(&p, g_xmh);  f16* xmh = (f16*)p;
    cudaGetSymbolAddress(&p, g_w1h);  f16* w1h = (f16*)p;
    cudaGetSymbolAddress(&p, g_w2h);  f16* w2h = (f16*)p;
    cudaGetSymbolAddress(&p, g_h);    float* hbuf = (float*)p;
    cudaGetSymbolAddress(&p, g_q1h);  f16* q1h = (f16*)p;
    cudaGetSymbolAddress(&p, g_k1h);  f16* k1h = (f16*)p;
    cudaGetSymbolAddress(&p, g_v1h);  f16* v1h = (f16*)p;
    cudaGetSymbolAddress(&p, g_q2);   float* q2b  = (float*)p;
    cudaGetSymbolAddress(&p, g_k2);   float* k2b  = (float*)p;
    cudaGetSymbolAddress(&p, g_s2);   float* s2b  = (float*)p;
    cudaGetSymbolAddress(&p, g_cch);  f16* cch = (f16*)p;
    cudaGetSymbolAddress(&p, g_out);  float* outb = (float*)p;

    static cudaStream_t s1 = nullptr;
    static cudaEvent_t evFork = nullptr, evW1 = nullptr, evLN = nullptr,
                       evPrep = nullptr, evSide = nullptr;
    if (s1 == nullptr) {
        cudaStreamCreateWithFlags(&s1, cudaStreamNonBlocking);
        cudaEventCreateWithFlags(&evFork, cudaEventDisableTiming);
        cudaEventCreateWithFlags(&evW1, cudaEventDisableTiming);
        cudaEventCreateWithFlags(&evLN, cudaEventDisableTiming);
        cudaEventCreateWithFlags(&evPrep, cudaEventDisableTiming);
        cudaEventCreateWithFlags(&evSide, cudaEventDisableTiming);
        cudaFuncSetAttribute(gemm_f16,
                             cudaFuncAttributeMaxDynamicSharedMemorySize, HG_SMEM);
        cudaFuncSetAttribute(flash1,
                             cudaFuncAttributeMaxDynamicSharedMemorySize, FLASH_SMEM);
    }

    const float scl = 0.08838834764831845f;  // 1/sqrt(128)

    // fork: side stream converts weights.
    // Convert only the qkv rows of w1 first so GEMM1_qkv can start ASAP;
    // the mlp rows and w2 convert afterward (consumed later, via stream order).
    cudaEventRecord(evFork, 0);
    cudaStreamWaitEvent(s1, evFork, 0);
    {
        int n4 = (QKVW * HIDDEN) / 4;
        convert_h<<<(n4 + 255) / 256, 256, 0, s1>>>(
            (const float4*)w1, (uint2*)w1h, n4);
    }
    cudaEventRecord(evW1, s1);
    {
        int n4 = (MLPH * HIDDEN) / 4;
        convert_h<<<(n4 + 255) / 256, 256, 0, s1>>>(
            (const float4*)(w1 + (size_t)QKVW * HIDDEN),
            (uint2*)(w1h + (size_t)QKVW * HIDDEN), n4);
        n4 = (HIDDEN * CCW) / 4;
        convert_h<<<(n4 + 255) / 256, 256, 0, s1>>>(
            (const float4*)w2, (uint2*)w2h, n4);
        zero_o2<<<(NHEADS * NC * HDIM + 255) / 256, 256, 0, s1>>>();
    }

    // main: modulation + layernorm
    mod_kernel<<<(3 * HIDDEN) / 8, 256>>>(vec, mod_w, mod_b);
    ln_mod_kernel<<<NROWS, 128>>>(x, concepts);
    cudaEventRecord(evLN, 0);

    // join w1_qkv, then qkv half of GEMM1 on main
    cudaStreamWaitEvent(0, evW1, 0);
    gemm_f16<<<dim3(QKVW / 128, (NROWS + 127) / 128), 256, HG_SMEM>>>(
        xmh, HIDDEN, w1h, HIDDEN,
        hbuf, QKVW, nullptr, QKVW,
        NROWS, QKVW, HIDDEN, b1);

    // side: mlp half of GEMM1 (after its conversion by stream order)
    cudaStreamWaitEvent(s1, evLN, 0);
    gemm_f16<<<dim3(MLPH / 128, (NROWS + 127) / 128), 256, HG_SMEM, s1>>>(
        xmh, HIDDEN, w1h + (size_t)QKVW * HIDDEN, HIDDEN,
        nullptr, 0, cch, 0,
        NROWS, MLPH, HIDDEN, b1 + QKVW);

    // side: GEMM2 over the MLP K-range; overlaps flash on main.
    gemm_f16<<<dim3(HIDDEN / 128, (NROWS + 127) / 128), 256, HG_SMEM, s1>>>(
        cch + HIDDEN, CCW, w2h + HIDDEN, CCW,
        outb, HIDDEN, nullptr, HIDDEN,
        NROWS, HIDDEN, MLPH, nullptr);

    // main: prep (warp-per-row) then flash
    attn_prep1<<<LX, 384>>>(pe, cpe, q_scale, k_scale);
    attn_prep2<<<NC, 384>>>(cpe, q_scale, k_scale);
    cudaEventRecord(evPrep, 0);

    // side: block-2 chain
    cudaStreamWaitEvent(s1, evPrep, 0);
    sgemm_abt<<<dim3((LC + 127) / 128, 1, NHEADS), 256, 0, s1>>>(
        q2b, HDIM, (long long)NC * HDIM, k2b, HDIM, (long long)LC * HDIM,
        s2b, LC, (long long)NC * LC, NC, LC, HDIM, scl);
    softmax_rows<<<NHEADS * NC, 256, 0, s1>>>(s2b, LC);
    pv2_kernel<<<dim3(KSPLIT, NHEADS), 256, 0, s1>>>();
    o2_to_cc<<<(NHEADS * NC * HDIM + 255) / 256, 256, 0, s1>>>();
    cudaEventRecord(evSide, s1);

    // main: flash attention
    flash1<<<dim3(LX / 128, NHEADS), 256, FLASH_SMEM>>>(q1h, k1h, v1h, cch);

    // join side (gemm2_mlp + block-2 done), then GEMM2 over attn K-range
    cudaStreamWaitEvent(0, evSide, 0);
    gemm_f16<<<dim3(HIDDEN / 128, (NROWS + 127) / 128), 256, HG_SMEM>>>(
        cch, CCW, w2h, CCW,
        outb + (size_t)NROWS * HIDDEN, HIDDEN, nullptr, HIDDEN,
        NROWS, HIDDEN, HIDDEN, nullptr);
    // residual + gate + bias + part sum
    final_kernel<<<(NROWS * (HIDDEN / 4) + 255) / 256, 256>>>(
        x, concepts, b2, out);
}

// round 16
// speedup vs baseline: 1.0613x; 1.0613x over previous
#include <cuda_runtime.h>
#include <cuda_fp16.h>
#include <math.h>
#include <stdint.h>

#define HIDDEN 1536
#define NHEADS 12
#define HDIM 128
#define MLPH 6144
#define TXT 256
#define LX 4352
#define NC 20
#define LC 4116
#define NROWS 4372          // LX + NC
#define W1OUT 10752         // 3*HIDDEN + MLPH
#define QKVW 4608           // 3*HIDDEN
#define CCW 7680            // HIDDEN + MLPH

typedef __half f16;

// ---------------- scratch (static device globals; no runtime allocation) ---
static __device__ float g_mod[3 * HIDDEN];
static __device__ f16   g_xmh[(size_t)NROWS * HIDDEN];
static __device__ f16   g_w1h[(size_t)W1OUT * HIDDEN];
static __device__ f16   g_w2h[(size_t)HIDDEN * CCW];
static __device__ float g_h[(size_t)NROWS * QKVW];
static __device__ f16   g_q1h[(size_t)NHEADS * LX * HDIM];
static __device__ f16   g_k1h[(size_t)NHEADS * LX * HDIM];
static __device__ f16   g_v1h[(size_t)NHEADS * LX * HDIM];
static __device__ float g_q2[(size_t)NHEADS * NC * HDIM];
static __device__ float g_k2[(size_t)NHEADS * LC * HDIM];
static __device__ float g_v2[(size_t)NHEADS * LC * HDIM];
static __device__ float g_s2[(size_t)NHEADS * NC * LC];
static __device__ float g_o2[(size_t)NHEADS * NC * HDIM];
static __device__ f16   g_cch[(size_t)NROWS * CCW];
static __device__ float g_out[(size_t)2 * NROWS * HIDDEN];   // GEMM2 K-parts

// ---------------- reductions ----------------------------------------------
__device__ __forceinline__ float warp_sum(float v) {
    #pragma unroll
    for (int o = 16; o > 0; o >>= 1) v += __shfl_xor_sync(0xffffffffu, v, o);
    return v;
}
__device__ __forceinline__ float warp_max(float v) {
    #pragma unroll
    for (int o = 16; o > 0; o >>= 1) v = fmaxf(v, __shfl_xor_sync(0xffffffffu, v, o));
    return v;
}
template <int NT>
__device__ __forceinline__ float block_sum(float v, float* sbuf) {
    v = warp_sum(v);
    int lane = threadIdx.x & 31, w = threadIdx.x >> 5;
    if (lane == 0) sbuf[w] = v;
    __syncthreads();
    if (threadIdx.x < 32) {
        float x = (threadIdx.x < NT / 32) ? sbuf[threadIdx.x] : 0.f;
        x = warp_sum(x);
        if (threadIdx.x == 0) sbuf[0] = x;
    }
    __syncthreads();
    float r = sbuf[0];
    __syncthreads();
    return r;
}
template <int NT>
__device__ __forceinline__ float block_max(float v, float* sbuf) {
    v = warp_max(v);
    int lane = threadIdx.x & 31, w = threadIdx.x >> 5;
    if (lane == 0) sbuf[w] = v;
    __syncthreads();
    if (threadIdx.x < 32) {
        float x = (threadIdx.x < NT / 32) ? sbuf[threadIdx.x] : -1e30f;
        x = warp_max(x);
        if (threadIdx.x == 0) sbuf[0] = x;
    }
    __syncthreads();
    float r = sbuf[0];
    __syncthreads();
    return r;
}

// ---------------- helpers ---------------------------------------------------
__device__ __forceinline__ uint32_t pack2h(float x, float y) {
    __half2 h = __halves2half2(__float2half_rn(x), __float2half_rn(y));
    return *reinterpret_cast<uint32_t*>(&h);
}
__device__ __forceinline__ float gelu_f(float xv) {
    float inner = 0.7978845608028654f * fmaf(0.044715f * xv * xv, xv, xv);
    return 0.5f * xv * (1.f + tanhf(inner));
}

// ======================= HMMA helpers ======================================
__device__ __forceinline__ uint32_t smem_u32(const void* p) {
    uint32_t a;
    asm("{ .reg .u64 t; cvta.to.shared.u64 t, %1; cvt.u32.u64 %0, t; }"
        : "=r"(a) : "l"(p));
    return a;
}
__device__ __forceinline__ void ldsm4(uint32_t* r, uint32_t addr) {
    asm volatile("ldmatrix.sync.aligned.m8n8.x4.shared.b16 {%0,%1,%2,%3}, [%4];"
                 : "=r"(r[0]), "=r"(r[1]), "=r"(r[2]), "=r"(r[3]) : "r"(addr));
}
__device__ __forceinline__ void ldsm4t(uint32_t* r, uint32_t addr) {
    asm volatile("ldmatrix.sync.aligned.m8n8.x4.trans.shared.b16 {%0,%1,%2,%3}, [%4];"
                 : "=r"(r[0]), "=r"(r[1]), "=r"(r[2]), "=r"(r[3]) : "r"(addr));
}
__device__ __forceinline__ void mma_f16(float* c, const uint32_t* a,
                                        uint32_t b0, uint32_t b1) {
    asm volatile(
        "mma.sync.aligned.m16n8k16.row.col.f32.f16.f16.f32 "
        "{%0,%1,%2,%3}, {%4,%5,%6,%7}, {%8,%9}, {%0,%1,%2,%3};"
        : "+f"(c[0]), "+f"(c[1]), "+f"(c[2]), "+f"(c[3])
        : "r"(a[0]), "r"(a[1]), "r"(a[2]), "r"(a[3]), "r"(b0), "r"(b1));
}
__device__ __forceinline__ void cp_async16(uint32_t dst, const void* src, int sz) {
    asm volatile("cp.async.cg.shared.global [%0], [%1], 16, %2;"
                 :: "r"(dst), "l"(src), "r"(sz) : "memory");
}
__device__ __forceinline__ void cp_commit() {
    asm volatile("cp.async.commit_group;" ::: "memory");
}
__device__ __forceinline__ void cp_wait1() {
    asm volatile("cp.async.wait_group 1;" ::: "memory");
}
__device__ __forceinline__ void cp_wait2() {
    asm volatile("cp.async.wait_group 2;" ::: "memory");
}

// smem: per stage 2 tiles (A, B): 128 rows x 32 f16, row stride 80 B
#define SPB      80
#define T_BYTES  (128 * SPB)          // 10240
#define STAGE_B  (2 * T_BYTES)        // 20480
#define NSTAGE   4
#define HG_SMEM  (NSTAGE * STAGE_B)   // 81920 -> 2 CTAs/SM

// ======== fp16 GEMM: C = A@B^T + bias ======================================
__global__ void __launch_bounds__(256, 2) gemm_f16(
    const f16* __restrict__ Ah, int lda,
    const f16* __restrict__ Bh, int ldb,
    float* __restrict__ C, int ldc,
    f16* __restrict__ Gh, int gelu_n0,
    int M, int N, int K, const float* __restrict__ bias)
{
    extern __shared__ char smem[];
    uint32_t sbase = smem_u32(smem);
    int tid = threadIdx.x, wid = tid >> 5, lane = tid & 31;

    const int GRP = 8;
    int npn = gridDim.x, npm = gridDim.y;
    int pid = blockIdx.y * npn + blockIdx.x;
    int gsz = GRP * npn;
    int gid = pid / gsz;
    int fm = gid * GRP;
    int gm = min(GRP, npm - fm);
    int pid_m = fm + (pid % gsz) % gm;
    int pid_n = (pid % gsz) / gm;
    int m0 = pid_m * 128, n0 = pid_n * 128;

    int warp_m = wid & 3;
    int warp_n = wid >> 2;
    int lrow = lane & 15, lhalf = lane >> 4;

    uint32_t a_off[2], b_off[4];
    #pragma unroll
    for (int i = 0; i < 2; ++i)
        a_off[i] = (uint32_t)((warp_m * 32 + i * 16 + lrow) * SPB + lhalf * 16);
    #pragma unroll
    for (int g = 0; g < 4; ++g)
        b_off[g] = (uint32_t)((warp_n * 64 + g * 16 + lrow) * SPB + lhalf * 16);

    float acc[2][8][4];
    #pragma unroll
    for (int i = 0; i < 2; ++i)
        #pragma unroll
        for (int j = 0; j < 8; ++j)
            #pragma unroll
            for (int t = 0; t < 4; ++t) acc[i][j][t] = 0.f;

    int nch = K >> 5;

    auto issue = [&](int c) {
        if (c < nch) {
            int kc = c << 5;
            uint32_t sb = sbase + (uint32_t)(c % NSTAGE) * STAGE_B;
            #pragma unroll
            for (int u4 = 0; u4 < 4; ++u4) {
                int u = tid + 256 * u4;
                int tile = u >> 9;              // 0=A, 1=B
                int r = (u >> 2) & 127;
                int c16 = u & 3;
                uint32_t dst = sb + (uint32_t)(tile * T_BYTES + r * SPB + c16 * 16);
                if (tile == 0) {
                    int sz = (m0 + r < M) ? 16 : 0;
                    cp_async16(dst, Ah + (size_t)(m0 + r) * lda + kc + c16 * 8, sz);
                } else {
                    cp_async16(dst, Bh + (size_t)(n0 + r) * ldb + kc + c16 * 8, 16);
                }
            }
        }
        cp_commit();
    };

    issue(0); issue(1); issue(2);

    for (int c = 0; c < nch; ++c) {
        cp_wait2();
        __syncthreads();
        issue(c + 3);
        uint32_t sb = sbase + (uint32_t)(c % NSTAGE) * STAGE_B;
        #pragma unroll
        for (int k16 = 0; k16 < 2; ++k16) {
            uint32_t koff = (uint32_t)(k16 * 32);
            uint32_t ah[2][4], bh[4][4];
            #pragma unroll
            for (int i = 0; i < 2; ++i)
                ldsm4(ah[i], sb + 0 * T_BYTES + a_off[i] + koff);
            #pragma unroll
            for (int g = 0; g < 4; ++g)
                ldsm4(bh[g], sb + 1 * T_BYTES + b_off[g] + koff);
            #pragma unroll
            for (int i = 0; i < 2; ++i)
                #pragma unroll
                for (int j = 0; j < 8; ++j) {
                    int g = j >> 1, sI = j & 1;
                    mma_f16(acc[i][j], ah[i], bh[g][sI], bh[g][sI + 2]);
                }
        }
    }

    int trow = lane >> 2, tc2 = (lane & 3) * 2;
    #pragma unroll
    for (int i = 0; i < 2; ++i) {
        #pragma unroll
        for (int half = 0; half < 2; ++half) {
            int m = m0 + warp_m * 32 + i * 16 + half * 8 + trow;
            if (m >= M) continue;
            #pragma unroll
            for (int j = 0; j < 8; ++j) {
                int n = n0 + warp_n * 64 + j * 8 + tc2;
                float vx = acc[i][j][half * 2 + 0];
                float vy = acc[i][j][half * 2 + 1];
                if (bias) { vx += bias[n]; vy += bias[n + 1]; }
                if (n >= gelu_n0) {
                    vx = gelu_f(vx); vy = gelu_f(vy);
                    int cc = HIDDEN + n - gelu_n0;
                    *reinterpret_cast<uint32_t*>(Gh + (size_t)m * CCW + cc) =
                        pack2h(vx, vy);
                } else {
                    *reinterpret_cast<float2*>(C + (size_t)m * ldc + n) =
                        make_float2(vx, vy);
                }
            }
        }
    }
}

// ================= flash attention for block 1 =============================
#define BK 64
#define FSTR 272                       // 128*2 + 16 pad
#define FQ_PLANE (128 * FSTR)          // 34816
#define FK_PLANE (BK * FSTR)           // 17408
#define FS_OFF   FQ_PLANE              // 34816
#define FSTAGE   (2 * FK_PLANE)        // 34816 (K + V)
#define FNS      3
#define FLASH_SMEM (FS_OFF + FNS * FSTAGE)  // 139264
#define NKT (LX / BK)                  // 68

__global__ void __launch_bounds__(256, 1) flash1(
    const f16* __restrict__ Qh,
    const f16* __restrict__ Kh, const f16* __restrict__ Vh,
    f16* __restrict__ Och)
{
    extern __shared__ char smem[];
    uint32_t sbase = smem_u32(smem);
    int tid = threadIdx.x, wid = tid >> 5, lane = tid & 31;
    int head = blockIdx.y;
    int q0 = blockIdx.x * 128;
    size_t hb = (size_t)head * LX * HDIM;
    const f16* qp0 = Qh + hb + (size_t)q0 * HDIM;
    const f16* kp[2] = { Kh + hb, Vh + hb };

    #pragma unroll
    for (int u8 = 0; u8 < 8; ++u8) {
        int u = tid + 256 * u8;
        int r = (u >> 4) & 127, c = u & 15;
        cp_async16(sbase + (uint32_t)(r * FSTR + c * 16),
                   qp0 + (size_t)r * HDIM + c * 8, 16);
    }
    cp_commit();

    auto issueKV = [&](int it) {
        if (it < NKT) {
            int kv0 = it * BK;
            #pragma unroll
            for (int u8 = 0; u8 < 8; ++u8) {
                int u = tid + 256 * u8;
                int pl = u >> 10, r = (u >> 4) & 63, c = u & 15;
                cp_async16(sbase + (uint32_t)(FS_OFF + (it % FNS) * FSTAGE +
                                              pl * FK_PLANE + r * FSTR + c * 16),
                           kp[pl] + (size_t)(kv0 + r) * HDIM + c * 8, 16);
            }
        }
        cp_commit();
    };
    issueKV(0);
    issueKV(1);

    uint32_t a_addr = sbase + (uint32_t)((wid * 16 + (lane & 15)) * FSTR +
                                         (lane >> 4) * 16);
    uint32_t bk_rel = (uint32_t)((lane & 15) * FSTR + (lane >> 4) * 16);
    uint32_t bv_rel = (uint32_t)(((((lane >> 3) & 1) * 8) + (lane & 7)) * FSTR +
                                 ((lane >> 4) & 1) * 16);

    float accO[16][4];
    #pragma unroll
    for (int j = 0; j < 16; ++j)
        #pragma unroll
        for (int t = 0; t < 4; ++t) accO[j][t] = 0.f;
    float mrow0 = -1e30f, mrow1 = -1e30f, lsum0 = 0.f, lsum1 = 0.f;
    const float scl = 0.08838834764831845f;

    for (int it = 0; it < NKT; ++it) {
        cp_wait1();
        __syncthreads();
        issueKV(it + 2);
        uint32_t kb = sbase + FS_OFF + (uint32_t)(it % FNS) * FSTAGE;

        float s[8][4];
        #pragma unroll
        for (int j = 0; j < 8; ++j)
            #pragma unroll
            for (int t = 0; t < 4; ++t) s[j][t] = 0.f;
        #pragma unroll
        for (int ks = 0; ks < 8; ++ks) {
            uint32_t aqh[4];
            ldsm4(aqh, a_addr + ks * 32);
            uint32_t bh[4][4];
            #pragma unroll
            for (int g = 0; g < 4; ++g)
                ldsm4(bh[g], kb + bk_rel + g * (16 * FSTR) + ks * 32);
            #pragma unroll
            for (int j = 0; j < 8; ++j)
                mma_f16(s[j], aqh, bh[j >> 1][j & 1], bh[j >> 1][(j & 1) + 2]);
        }

        float m0 = -1e30f, m1 = -1e30f;
        #pragma unroll
        for (int j = 0; j < 8; ++j) {
            s[j][0] *= scl; s[j][1] *= scl; s[j][2] *= scl; s[j][3] *= scl;
            m0 = fmaxf(m0, fmaxf(s[j][0], s[j][1]));
            m1 = fmaxf(m1, fmaxf(s[j][2], s[j][3]));
        }
        m0 = fmaxf(m0, __shfl_xor_sync(0xffffffffu, m0, 1));
        m0 = fmaxf(m0, __shfl_xor_sync(0xffffffffu, m0, 2));
        m1 = fmaxf(m1, __shfl_xor_sync(0xffffffffu, m1, 1));
        m1 = fmaxf(m1, __shfl_xor_sync(0xffffffffu, m1, 2));
        float mn0 = fmaxf(mrow0, m0), mn1 = fmaxf(mrow1, m1);
        float al0 = __expf(mrow0 - mn0), al1 = __expf(mrow1 - mn1);
        mrow0 = mn0; mrow1 = mn1;

        uint32_t ph[8][2];
        float ps0 = 0.f, ps1 = 0.f;
        #pragma unroll
        for (int j = 0; j < 8; ++j) {
            float p00 = __expf(s[j][0] - mn0), p01 = __expf(s[j][1] - mn0);
            float p10 = __expf(s[j][2] - mn1), p11 = __expf(s[j][3] - mn1);
            ps0 += p00 + p01; ps1 += p10 + p11;
            ph[j][0] = pack2h(p00, p01);
            ph[j][1] = pack2h(p10, p11);
        }
        lsum0 = lsum0 * al0 + ps0;
        lsum1 = lsum1 * al1 + ps1;
        #pragma unroll
        for (int j = 0; j < 16; ++j) {
            accO[j][0] *= al0; accO[j][1] *= al0;
            accO[j][2] *= al1; accO[j][3] *= al1;
        }

        uint32_t vb = kb + FK_PLANE;
        #pragma unroll
        for (int s4 = 0; s4 < 4; ++s4) {
            uint32_t Ahf[4] = { ph[2 * s4][0], ph[2 * s4][1],
                                ph[2 * s4 + 1][0], ph[2 * s4 + 1][1] };
            #pragma unroll
            for (int g = 0; g < 8; ++g) {
                uint32_t bvh[4];
                ldsm4t(bvh, vb + bv_rel + s4 * (16 * FSTR) + g * 32);
                mma_f16(accO[2 * g],     Ahf, bvh[0], bvh[1]);
                mma_f16(accO[2 * g + 1], Ahf, bvh[2], bvh[3]);
            }
        }
    }

    lsum0 += __shfl_xor_sync(0xffffffffu, lsum0, 1);
    lsum0 += __shfl_xor_sync(0xffffffffu, lsum0, 2);
    lsum1 += __shfl_xor_sync(0xffffffffu, lsum1, 1);
    lsum1 += __shfl_xor_sync(0xffffffffu, lsum1, 2);
    float inv0 = 1.f / lsum0, inv1 = 1.f / lsum1;
    int r0 = q0 + wid * 16 + (lane >> 2);
    int cbase = head * HDIM + (lane & 3) * 2;
    #pragma unroll
    for (int j = 0; j < 16; ++j) {
        int c = cbase + j * 8;
        *reinterpret_cast<uint32_t*>(Och + (size_t)r0 * CCW + c) =
            pack2h(accO[j][0] * inv0, accO[j][1] * inv0);
        *reinterpret_cast<uint32_t*>(Och + (size_t)(r0 + 8) * CCW + c) =
            pack2h(accO[j][2] * inv1, accO[j][3] * inv1);
    }
}

// ---------------- SIMT GEMM (block-2 QK^T only) ----------------------------
__global__ void __launch_bounds__(256) sgemm_abt(
    const float* __restrict__ A, int lda, long long sA,
    const float* __restrict__ B, int ldb, long long sB,
    float* __restrict__ C, int ldc, long long sC,
    int M, int N, int K, float alpha)
{
    __shared__ float As[8][128];
    __shared__ float Bs[8][128];
    int bz = blockIdx.z;
    A += (size_t)sA * bz;
    B += (size_t)sB * bz;
    C += (size_t)sC * bz;
    int m0 = blockIdx.y * 128;
    int n0 = blockIdx.x * 128;
    int tid = threadIdx.x;
    int tx = tid & 15, ty = tid >> 4;
    int lrow = tid >> 1;
    int lcol = (tid & 1) * 4;

    float acc[8][8];
    #pragma unroll
    for (int i = 0; i < 8; i++)
        #pragma unroll
        for (int j = 0; j < 8; j++) acc[i][j] = 0.f;

    for (int k0 = 0; k0 < K; k0 += 8) {
        float4 av = make_float4(0.f, 0.f, 0.f, 0.f);
        float4 bv = make_float4(0.f, 0.f, 0.f, 0.f);
        if (m0 + lrow < M && k0 + lcol < K)
            av = *reinterpret_cast<const float4*>(A + (size_t)(m0 + lrow) * lda + k0 + lcol);
        if (n0 + lrow < N && k0 + lcol < K)
            bv = *reinterpret_cast<const float4*>(B + (size_t)(n0 + lrow) * ldb + k0 + lcol);
        As[lcol + 0][lrow] = av.x; As[lcol + 1][lrow] = av.y;
        As[lcol + 2][lrow] = av.z; As[lcol + 3][lrow] = av.w;
        Bs[lcol + 0][lrow] = bv.x; Bs[lcol + 1][lrow] = bv.y;
        Bs[lcol + 2][lrow] = bv.z; Bs[lcol + 3][lrow] = bv.w;
        __syncthreads();
        #pragma unroll
        for (int k = 0; k < 8; k++) {
            float ra[8], rb[8];
            #pragma unroll
            for (int i = 0; i < 8; i++) ra[i] = As[k][ty + 16 * i];
            #pragma unroll
            for (int j = 0; j < 8; j++) rb[j] = Bs[k][tx + 16 * j];
            #pragma unroll
            for (int i = 0; i < 8; i++)
                #pragma unroll
                for (int j = 0; j < 8; j++)
                    acc[i][j] = fmaf(ra[i], rb[j], acc[i][j]);
        }
        __syncthreads();
    }

    #pragma unroll
    for (int i = 0; i < 8; i++) {
        int m = m0 + ty + 16 * i;
        if (m >= M) continue;
        #pragma unroll
        for (int j = 0; j < 8; j++) {
            int n = n0 + tx + 16 * j;
            if (n >= N) continue;
            C[(size_t)m * ldc + n] = alpha * acc[i][j];
        }
    }
}

// ---------------- block-2 PV: split-K rank-1 updates -----------------------
#define KSPLIT 16
__global__ void __launch_bounds__(256) zero_o2()
{
    int idx = blockIdx.x * 256 + threadIdx.x;
    if (idx < NHEADS * NC * HDIM) g_o2[idx] = 0.f;
}
__global__ void __launch_bounds__(256) pv2_kernel()
{
    int h = blockIdx.y, ks = blockIdx.x;
    int chunk = (LC + KSPLIT - 1) / KSPLIT;
    int k0 = ks * chunk, k1 = min(LC, k0 + chunk);
    int d = threadIdx.x & 127, g = threadIdx.x >> 7;
    const float* S = g_s2 + (size_t)h * NC * LC;
    const float* V = g_v2 + (size_t)h * LC * HDIM;
    float acc[10];
    #pragma unroll
    for (int i = 0; i < 10; ++i) acc[i] = 0.f;
    for (int k = k0; k < k1; ++k) {
        float v = V[(size_t)k * HDIM + d];
        #pragma unroll
        for (int i = 0; i < 10; ++i)
            acc[i] = fmaf(__ldg(S + (size_t)(g * 10 + i) * LC + k), v, acc[i]);
    }
    #pragma unroll
    for (int i = 0; i < 10; ++i)
        atomicAdd(&g_o2[((size_t)h * NC + g * 10 + i) * HDIM + d], acc[i]);
}
__global__ void __launch_bounds__(256) o2_to_cc()
{
    int idx = blockIdx.x * 256 + threadIdx.x;
    if (idx >= NHEADS * NC * HDIM) return;
    int d = idx & 127;
    int i = (idx >> 7) % NC;
    int h = idx / (NC * HDIM);
    g_cch[(size_t)(LX + i) * CCW + h * HDIM + d] = __float2half_rn(g_o2[idx]);
}

// ---------------- convert fp32 -> fp16 -------------------------------------
__global__ void __launch_bounds__(256) convert_h(
    const float4* __restrict__ src, uint2* __restrict__ h, int n4)
{
    int idx = blockIdx.x * 256 + threadIdx.x;
    if (idx >= n4) return;
    float4 v = src[idx];
    uint2 r;
    r.x = pack2h(v.x, v.y);
    r.y = pack2h(v.z, v.w);
    h[idx] = r;
}

// ---------------- modulation: m = silu(vec) @ mod_w^T + mod_b --------------
__global__ void __launch_bounds__(256) mod_kernel(
    const float* __restrict__ vec, const float* __restrict__ mod_w,
    const float* __restrict__ mod_b)
{
    __shared__ float sv[HIDDEN];
    for (int i = threadIdx.x; i < HIDDEN; i += 256) {
        float xv = vec[i];
        sv[i] = xv / (1.f + __expf(-xv));
    }
    __syncthreads();
    int n = blockIdx.x * 8 + (threadIdx.x >> 5);
    int lane = threadIdx.x & 31;
    const float4* w4 = reinterpret_cast<const float4*>(mod_w + (size_t)n * HIDDEN);
    float acc = 0.f;
    #pragma unroll
    for (int i = 0; i < 12; ++i) {
        float4 w = w4[lane + 32 * i];
        int k = (lane + 32 * i) * 4;
        acc += w.x * sv[k] + w.y * sv[k + 1] + w.z * sv[k + 2] + w.w * sv[k + 3];
    }
    acc = warp_sum(acc);
    if (lane == 0) g_mod[n] = acc + mod_b[n];
}

// ---------------- layernorm + modulate -> fp16 (float4) ---------------------
__global__ void __launch_bounds__(128) ln_mod_kernel(
    const float* __restrict__ x, const float* __restrict__ concepts)
{
    __shared__ float sbuf[4];
    int row = blockIdx.x;
    const float4* src = (row < LX)
        ? reinterpret_cast<const float4*>(x + (size_t)row * HIDDEN)
        : reinterpret_cast<const float4*>(concepts + (size_t)(row - LX) * HIDDEN);
    int tid = threadIdx.x;
    float4 v[3];
    float s = 0.f;
    #pragma unroll
    for (int i = 0; i < 3; i++) {
        v[i] = src[tid + 128 * i];
        s += v[i].x + v[i].y + v[i].z + v[i].w;
    }
    s = block_sum<128>(s, sbuf);
    float mu = s * (1.0f / 1536.0f);
    float s2 = 0.f;
    #pragma unroll
    for (int i = 0; i < 3; i++) {
        float dx = v[i].x - mu, dy = v[i].y - mu, dz = v[i].z - mu, dw = v[i].w - mu;
        s2 = fmaf(dx, dx, s2); s2 = fmaf(dy, dy, s2);
        s2 = fmaf(dz, dz, s2); s2 = fmaf(dw, dw, s2);
    }
    s2 = block_sum<128>(s2, sbuf);
    float rstd = rsqrtf(s2 * (1.0f / 1536.0f) + 1e-6f);
    #pragma unroll
    for (int i = 0; i < 3; i++) {
        int j4 = tid + 128 * i;
        float4 sc = *reinterpret_cast<const float4*>(g_mod + HIDDEN + j4 * 4);
        float4 sh = *reinterpret_cast<const float4*>(g_mod + j4 * 4);
        float ox = (1.f + sc.x) * ((v[i].x - mu) * rstd) + sh.x;
        float oy = (1.f + sc.y) * ((v[i].y - mu) * rstd) + sh.y;
        float oz = (1.f + sc.z) * ((v[i].z - mu) * rstd) + sh.z;
        float ow = (1.f + sc.w) * ((v[i].w - mu) * rstd) + sh.w;
        uint2 r;
        r.x = pack2h(ox, oy);
        r.y = pack2h(oz, ow);
        *reinterpret_cast<uint2*>(g_xmh + (size_t)row * HIDDEN + j4 * 4) = r;
    }
}

// ---------------- attention prep (warp per token-head, float4) -------------
__device__ __forceinline__ float4 rope4(float4 t, const float* __restrict__ pe,
                                        int tok, int lane)
{
    float4 p0 = *reinterpret_cast<const float4*>(pe + ((size_t)tok * 64 + lane * 2) * 4);
    float4 p1 = *reinterpret_cast<const float4*>(pe + ((size_t)tok * 64 + lane * 2 + 1) * 4);
    float4 r;
    r.x = p0.x * t.x + p0.y * t.y;
    r.y = p0.z * t.x + p0.w * t.y;
    r.z = p1.x * t.z + p1.y * t.w;
    r.w = p1.z * t.z + p1.w * t.w;
    return r;
}

__global__ void __launch_bounds__(384) attn_prep1(
    const float* __restrict__ pe, const float* __restrict__ cpe,
    const float* __restrict__ q_scale, const float* __restrict__ k_scale)
{
    int t = blockIdx.x;
    int h = threadIdx.x >> 5, lane = threadIdx.x & 31;
    const float* hrow = g_h + (size_t)t * QKVW;
    float4 q = *reinterpret_cast<const float4*>(hrow + h * HDIM + lane * 4);
    float4 k = *reinterpret_cast<const float4*>(hrow + HIDDEN + h * HDIM + lane * 4);
    float4 v = *reinterpret_cast<const float4*>(hrow + 2 * HIDDEN + h * HDIM + lane * 4);
    float sq = q.x * q.x + q.y * q.y + q.z * q.z + q.w * q.w;
    float sk = k.x * k.x + k.y * k.y + k.z * k.z + k.w * k.w;
    sq = warp_sum(sq); sk = warp_sum(sk);
    float rq = rsqrtf(sq * (1.f / 128.f) + 1e-6f);
    float rk = rsqrtf(sk * (1.f / 128.f) + 1e-6f);
    float4 qs = *reinterpret_cast<const float4*>(q_scale + lane * 4);
    float4 ks = *reinterpret_cast<const float4*>(k_scale + lane * 4);
    float4 qn = make_float4(q.x * rq * qs.x, q.y * rq * qs.y,
                            q.z * rq * qs.z, q.w * rq * qs.w);
    float4 kn = make_float4(k.x * rk * ks.x, k.y * rk * ks.y,
                            k.z * rk * ks.z, k.w * rk * ks.w);
    float4 qr = rope4(qn, pe, t, lane);
    float4 kr = rope4(kn, pe, t, lane);
    size_t qi = ((size_t)h * LX + t) * HDIM + lane * 4;
    uint2 r;
    r.x = pack2h(qr.x, qr.y); r.y = pack2h(qr.z, qr.w);
    *reinterpret_cast<uint2*>(g_q1h + qi) = r;
    r.x = pack2h(kr.x, kr.y); r.y = pack2h(kr.z, kr.w);
    *reinterpret_cast<uint2*>(g_k1h + qi) = r;
    r.x = pack2h(v.x, v.y); r.y = pack2h(v.z, v.w);
    *reinterpret_cast<uint2*>(g_v1h + qi) = r;
    if (t >= TXT) {
        int j = NC + (t - TXT);
        float4 kc = rope4(kn, cpe, j, lane);
        size_t ki = ((size_t)h * LC + j) * HDIM + lane * 4;
        *reinterpret_cast<float4*>(g_k2 + ki) = kc;
        *reinterpret_cast<float4*>(g_v2 + ki) = v;
    }
}

__global__ void __launch_bounds__(384) attn_prep2(
    const float* __restrict__ cpe,
    const float* __restrict__ q_scale, const float* __restrict__ k_scale)
{
    int i = blockIdx.x;
    int h = threadIdx.x >> 5, lane = threadIdx.x & 31;
    const float* hrow = g_h + (size_t)(LX + i) * QKVW;
    float4 q = *reinterpret_cast<const float4*>(hrow + h * HDIM + lane * 4);
    float4 k = *reinterpret_cast<const float4*>(hrow + HIDDEN + h * HDIM + lane * 4);
    float4 v = *reinterpret_cast<const float4*>(hrow + 2 * HIDDEN + h * HDIM + lane * 4);
    float sq = q.x * q.x + q.y * q.y + q.z * q.z + q.w * q.w;
    float sk = k.x * k.x + k.y * k.y + k.z * k.z + k.w * k.w;
    sq = warp_sum(sq); sk = warp_sum(sk);
    float rq = rsqrtf(sq * (1.f / 128.f) + 1e-6f);
    float rk = rsqrtf(sk * (1.f / 128.f) + 1e-6f);
    float4 qs = *reinterpret_cast<const float4*>(q_scale + lane * 4);
    float4 ks = *reinterpret_cast<const float4*>(k_scale + lane * 4);
    float4 qn = make_float4(q.x * rq * qs.x, q.y * rq * qs.y,
                            q.z * rq * qs.z, q.w * rq * qs.w);
    float4 kn = make_float4(k.x * rk * ks.x, k.y * rk * ks.y,
                            k.z * rk * ks.z, k.w * rk * ks.w);
    float4 qr = rope4(qn, cpe, i, lane);
    float4 kr = rope4(kn, cpe, i, lane);
    *reinterpret_cast<float4*>(g_q2 + ((size_t)h * NC + i) * HDIM + lane * 4) = qr;
    size_t ki = ((size_t)h * LC + i) * HDIM + lane * 4;
    *reinterpret_cast<float4*>(g_k2 + ki) = kr;
    *reinterpret_cast<float4*>(g_v2 + ki) = v;
}

// ---------------- row softmax (block-2 path) -------------------------------
__global__ void __launch_bounds__(256) softmax_rows(float* __restrict__ S, int ncol)
{
    __shared__ float sbuf[8];
    float* row = S + (size_t)blockIdx.x * ncol;
    int tid = threadIdx.x;
    float v[17];
    float mx = -1e30f;
    #pragma unroll
    for (int i = 0; i < 17; i++) {
        int c = tid + 256 * i;
        v[i] = (c < ncol) ? row[c] : -1e30f;
        mx = fmaxf(mx, v[i]);
    }
    mx = block_max<256>(mx, sbuf);
    float s = 0.f;
    #pragma unroll
    for (int i = 0; i < 17; i++) { v[i] = __expf(v[i] - mx); s += v[i]; }
    s = block_sum<256>(s, sbuf);
    float inv = 1.f / s;
    #pragma unroll
    for (int i = 0; i < 17; i++) {
        int c = tid + 256 * i;
        if (c < ncol) row[c] = v[i] * inv;
    }
}

// ---------------- residual: out = base + gate*(p0 + p1 + b2) (float4) ------
__global__ void __launch_bounds__(256) final_kernel(
    const float* __restrict__ x, const float* __restrict__ concepts,
    const float* __restrict__ b2, float* __restrict__ out)
{
    int idx = blockIdx.x * 256 + threadIdx.x;      // float4 index
    if (idx >= NROWS * (HIDDEN / 4)) return;
    int c4 = idx % (HIDDEN / 4);
    int r = idx / (HIDDEN / 4);
    float4 base = (r < LX)
        ? reinterpret_cast<const float4*>(x)[idx]
        : reinterpret_cast<const float4*>(concepts)[idx - LX * (HIDDEN / 4)];
    float4 g = *reinterpret_cast<const float4*>(g_mod + 2 * HIDDEN + c4 * 4);
    float4 bb = reinterpret_cast<const float4*>(b2)[c4];
    float4 p0 = reinterpret_cast<const float4*>(g_out)[idx];
    float4 p1 = reinterpret_cast<const float4*>(g_out)[idx + NROWS * (HIDDEN / 4)];
    float4 rv;
    rv.x = fmaf(g.x, p0.x + p1.x + bb.x, base.x);
    rv.y = fmaf(g.y, p0.y + p1.y + bb.y, base.y);
    rv.z = fmaf(g.z, p0.z + p1.z + bb.z, base.z);
    rv.w = fmaf(g.w, p0.w + p1.w + bb.w, base.w);
    reinterpret_cast<float4*>(out)[idx] = rv;
}

// ---------------------------------------------------------------------------
extern "C" void kernel_launch(void* const* d_in, const int* in_sizes, int n_in,
                              void* d_out, int out_size)
{
    const float* x        = (const float*)d_in[0];
    const float* concepts = (const float*)d_in[1];
    const float* vec      = (const float*)d_in[2];
    const float* pe       = (const float*)d_in[3];
    const float* cpe      = (const float*)d_in[4];
    const float* w1       = (const float*)d_in[5];
    const float* b1       = (const float*)d_in[6];
    const float* w2       = (const float*)d_in[7];
    const float* b2       = (const float*)d_in[8];
    const float* q_scale  = (const float*)d_in[9];
    const float* k_scale  = (const float*)d_in[10];
    const float* mod_w    = (const float*)d_in[11];
    const float* mod_b    = (const float*)d_in[12];
    float* out = (float*)d_out;

    void* p;
    cudaGetSymbolAddress(&p, g_xmh);  f16* xmh = (f16*)p;
    cudaGetSymbolAddress(&p, g_w1h);  f16* w1h = (f16*)p;
    cudaGetSymbolAddress(&p, g_w2h);  f16* w2h = (f16*)p;
    cudaGetSymbolAddress(&p, g_h);    float* hbuf = (float*)p;
    cudaGetSymbolAddress(&p, g_q1h);  f16* q1h = (f16*)p;
    cudaGetSymbolAddress(&p, g_k1h);  f16* k1h = (f16*)p;
    cudaGetSymbolAddress(&p, g_v1h);  f16* v1h = (f16*)p;
    cudaGetSymbolAddress(&p, g_q2);   float* q2b  = (float*)p;
    cudaGetSymbolAddress(&p, g_k2);   float* k2b  = (float*)p;
    cudaGetSymbolAddress(&p, g_s2);   float* s2b  = (float*)p;
    cudaGetSymbolAddress(&p, g_cch);  f16* cch = (f16*)p;
    cudaGetSymbolAddress(&p, g_out);  float* outb = (float*)p;

    static cudaStream_t s1 = nullptr;
    static cudaEvent_t evFork = nullptr, evW1 = nullptr, evLN = nullptr,
                       evPrep = nullptr, evSide = nullptr;
    if (s1 == nullptr) {
        cudaStreamCreateWithFlags(&s1, cudaStreamNonBlocking);
        cudaEventCreateWithFlags(&evFork, cudaEventDisableTiming);
        cudaEventCreateWithFlags(&evW1, cudaEventDisableTiming);
        cudaEventCreateWithFlags(&evLN, cudaEventDisableTiming);
        cudaEventCreateWithFlags(&evPrep, cudaEventDisableTiming);
        cudaEventCreateWithFlags(&evSide, cudaEventDisableTiming);
        cudaFuncSetAttribute(gemm_f16,
                             cudaFuncAttributeMaxDynamicSharedMemorySize, HG_SMEM);
        cudaFuncSetAttribute(flash1,
                             cudaFuncAttributeMaxDynamicSharedMemorySize, FLASH_SMEM);
    }

    const float scl = 0.08838834764831845f;  // 1/sqrt(128)

    // fork: side stream converts weights (full w1 before evW1 — R14 schedule)
    cudaEventRecord(evFork, 0);
    cudaStreamWaitEvent(s1, evFork, 0);
    {
        int n4 = (W1OUT * HIDDEN) / 4;
        convert_h<<<(n4 + 255) / 256, 256, 0, s1>>>(
            (const float4*)w1, (uint2*)w1h, n4);
    }
    cudaEventRecord(evW1, s1);
    {
        int n4 = (HIDDEN * CCW) / 4;
        convert_h<<<(n4 + 255) / 256, 256, 0, s1>>>(
            (const float4*)w2, (uint2*)w2h, n4);
        zero_o2<<<(NHEADS * NC * HDIM + 255) / 256, 256, 0, s1>>>();
    }

    // main: modulation + layernorm
    mod_kernel<<<(3 * HIDDEN) / 8, 256>>>(vec, mod_w, mod_b);
    ln_mod_kernel<<<NROWS, 128>>>(x, concepts);
    cudaEventRecord(evLN, 0);

    // join w1, then qkv half of GEMM1 on main
    cudaStreamWaitEvent(0, evW1, 0);
    gemm_f16<<<dim3(QKVW / 128, (NROWS + 127) / 128), 256, HG_SMEM>>>(
        xmh, HIDDEN, w1h, HIDDEN,
        hbuf, QKVW, nullptr, QKVW,
        NROWS, QKVW, HIDDEN, b1);

    // side: mlp half of GEMM1 (overlaps prep + flash)
    cudaStreamWaitEvent(s1, evLN, 0);
    gemm_f16<<<dim3(MLPH / 128, (NROWS + 127) / 128), 256, HG_SMEM, s1>>>(
        xmh, HIDDEN, w1h + (size_t)QKVW * HIDDEN, HIDDEN,
        nullptr, 0, cch, 0,
        NROWS, MLPH, HIDDEN, b1 + QKVW);

    // side: GEMM2 over the MLP K-range; overlaps flash on main.
    gemm_f16<<<dim3(HIDDEN / 128, (NROWS + 127) / 128), 256, HG_SMEM, s1>>>(
        cch + HIDDEN, CCW, w2h + HIDDEN, CCW,
        outb, HIDDEN, nullptr, HIDDEN,
        NROWS, HIDDEN, MLPH, nullptr);

    // main: prep (warp-per-row) then flash
    attn_prep1<<<LX, 384>>>(pe, cpe, q_scale, k_scale);
    attn_prep2<<<NC, 384>>>(cpe, q_scale, k_scale);
    cudaEventRecord(evPrep, 0);

    // side: block-2 chain
    cudaStreamWaitEvent(s1, evPrep, 0);
    sgemm_abt<<<dim3((LC + 127) / 128, 1, NHEADS), 256, 0, s1>>>(
        q2b, HDIM, (long long)NC * HDIM, k2b, HDIM, (long long)LC * HDIM,
        s2b, LC, (long long)NC * LC, NC, LC, HDIM, scl);
    softmax_rows<<<NHEADS * NC, 256, 0, s1>>>(s2b, LC);
    pv2_kernel<<<dim3(KSPLIT, NHEADS), 256, 0, s1>>>();
    o2_to_cc<<<(NHEADS * NC * HDIM + 255) / 256, 256, 0, s1>>>();
    cudaEventRecord(evSide, s1);

    // main: flash attention
    flash1<<<dim3(LX / 128, NHEADS), 256, FLASH_SMEM>>>(q1h, k1h, v1h, cch);

    // join side (gemm2_mlp + block-2 done), then GEMM2 over attn K-range
    cudaStreamWaitEvent(0, evSide, 0);
    gemm_f16<<<dim3(HIDDEN / 128, (NROWS + 127) / 128), 256, HG_SMEM>>>(
        cch, CCW, w2h, CCW,
        outb + (size_t)NROWS * HIDDEN, HIDDEN, nullptr, HIDDEN,
        NROWS, HIDDEN, HIDDEN, nullptr);
    // residual + gate + bias + part sum
    final_kernel<<<(NROWS * (HIDDEN / 4) + 255) / 256, 256>>>(
        x, concepts, b2, out);
}

// round 17
// speedup vs baseline: 1.0623x; 1.0010x over previous
#include <cuda_runtime.h>
#include <cuda_fp16.h>
#include <math.h>
#include <stdint.h>

#define HIDDEN 1536
#define NHEADS 12
#define HDIM 128
#define MLPH 6144
#define TXT 256
#define LX 4352
#define NC 20
#define LC 4116
#define NROWS 4372          // LX + NC
#define W1OUT 10752         // 3*HIDDEN + MLPH
#define QKVW 4608           // 3*HIDDEN
#define CCW 7680            // HIDDEN + MLPH

typedef __half f16;

// ---------------- scratch (static device globals; no runtime allocation) ---
static __device__ float g_mod[3 * HIDDEN];
static __device__ f16   g_xmh[(size_t)NROWS * HIDDEN];
static __device__ f16   g_w1h[(size_t)W1OUT * HIDDEN];
static __device__ f16   g_w2h[(size_t)HIDDEN * CCW];
static __device__ float g_h[(size_t)NROWS * QKVW];
static __device__ f16   g_q1h[(size_t)NHEADS * LX * HDIM];
static __device__ f16   g_k1h[(size_t)NHEADS * LX * HDIM];
static __device__ f16   g_v1h[(size_t)NHEADS * LX * HDIM];
static __device__ float g_q2[(size_t)NHEADS * NC * HDIM];
static __device__ float g_k2[(size_t)NHEADS * LC * HDIM];
static __device__ float g_v2[(size_t)NHEADS * LC * HDIM];
static __device__ float g_s2[(size_t)NHEADS * NC * LC];
static __device__ float g_o2[(size_t)NHEADS * NC * HDIM];
static __device__ f16   g_cch[(size_t)NROWS * CCW];
static __device__ float g_out[(size_t)2 * NROWS * HIDDEN];   // GEMM2 K-parts

// ---------------- reductions ----------------------------------------------
__device__ __forceinline__ float warp_sum(float v) {
    #pragma unroll
    for (int o = 16; o > 0; o >>= 1) v += __shfl_xor_sync(0xffffffffu, v, o);
    return v;
}
__device__ __forceinline__ float warp_max(float v) {
    #pragma unroll
    for (int o = 16; o > 0; o >>= 1) v = fmaxf(v, __shfl_xor_sync(0xffffffffu, v, o));
    return v;
}
template <int NT>
__device__ __forceinline__ float block_sum(float v, float* sbuf) {
    v = warp_sum(v);
    int lane = threadIdx.x & 31, w = threadIdx.x >> 5;
    if (lane == 0) sbuf[w] = v;
    __syncthreads();
    if (threadIdx.x < 32) {
        float x = (threadIdx.x < NT / 32) ? sbuf[threadIdx.x] : 0.f;
        x = warp_sum(x);
        if (threadIdx.x == 0) sbuf[0] = x;
    }
    __syncthreads();
    float r = sbuf[0];
    __syncthreads();
    return r;
}
template <int NT>
__device__ __forceinline__ float block_max(float v, float* sbuf) {
    v = warp_max(v);
    int lane = threadIdx.x & 31, w = threadIdx.x >> 5;
    if (lane == 0) sbuf[w] = v;
    __syncthreads();
    if (threadIdx.x < 32) {
        float x = (threadIdx.x < NT / 32) ? sbuf[threadIdx.x] : -1e30f;
        x = warp_max(x);
        if (threadIdx.x == 0) sbuf[0] = x;
    }
    __syncthreads();
    float r = sbuf[0];
    __syncthreads();
    return r;
}

// ---------------- helpers ---------------------------------------------------
__device__ __forceinline__ uint32_t pack2h(float x, float y) {
    __half2 h = __halves2half2(__float2half_rn(x), __float2half_rn(y));
    return *reinterpret_cast<uint32_t*>(&h);
}
__device__ __forceinline__ float gelu_f(float xv) {
    float inner = 0.7978845608028654f * fmaf(0.044715f * xv * xv, xv, xv);
    return 0.5f * xv * (1.f + tanhf(inner));
}

// ======================= HMMA helpers ======================================
__device__ __forceinline__ uint32_t smem_u32(const void* p) {
    uint32_t a;
    asm("{ .reg .u64 t; cvta.to.shared.u64 t, %1; cvt.u32.u64 %0, t; }"
        : "=r"(a) : "l"(p));
    return a;
}
__device__ __forceinline__ void ldsm4(uint32_t* r, uint32_t addr) {
    asm volatile("ldmatrix.sync.aligned.m8n8.x4.shared.b16 {%0,%1,%2,%3}, [%4];"
                 : "=r"(r[0]), "=r"(r[1]), "=r"(r[2]), "=r"(r[3]) : "r"(addr));
}
__device__ __forceinline__ void ldsm4t(uint32_t* r, uint32_t addr) {
    asm volatile("ldmatrix.sync.aligned.m8n8.x4.trans.shared.b16 {%0,%1,%2,%3}, [%4];"
                 : "=r"(r[0]), "=r"(r[1]), "=r"(r[2]), "=r"(r[3]) : "r"(addr));
}
__device__ __forceinline__ void mma_f16(float* c, const uint32_t* a,
                                        uint32_t b0, uint32_t b1) {
    asm volatile(
        "mma.sync.aligned.m16n8k16.row.col.f32.f16.f16.f32 "
        "{%0,%1,%2,%3}, {%4,%5,%6,%7}, {%8,%9}, {%0,%1,%2,%3};"
        : "+f"(c[0]), "+f"(c[1]), "+f"(c[2]), "+f"(c[3])
        : "r"(a[0]), "r"(a[1]), "r"(a[2]), "r"(a[3]), "r"(b0), "r"(b1));
}
__device__ __forceinline__ void cp_async16(uint32_t dst, const void* src, int sz) {
    asm volatile("cp.async.cg.shared.global [%0], [%1], 16, %2;"
                 :: "r"(dst), "l"(src), "r"(sz) : "memory");
}
__device__ __forceinline__ void cp_commit() {
    asm volatile("cp.async.commit_group;" ::: "memory");
}
__device__ __forceinline__ void cp_wait1() {
    asm volatile("cp.async.wait_group 1;" ::: "memory");
}
__device__ __forceinline__ void cp_wait2() {
    asm volatile("cp.async.wait_group 2;" ::: "memory");
}

// smem: per stage 2 tiles (A, B): 128 rows x 32 f16, row stride 80 B
#define SPB      80
#define T_BYTES  (128 * SPB)          // 10240
#define STAGE_B  (2 * T_BYTES)        // 20480
#define NSTAGE   4
#define HG_SMEM  (NSTAGE * STAGE_B)   // 81920 -> 2 CTAs/SM

// ======== fp16 GEMM: C = A@B^T + bias ======================================
__global__ void __launch_bounds__(256, 2) gemm_f16(
    const f16* __restrict__ Ah, int lda,
    const f16* __restrict__ Bh, int ldb,
    float* __restrict__ C, int ldc,
    f16* __restrict__ Gh, int gelu_n0,
    int M, int N, int K, const float* __restrict__ bias)
{
    extern __shared__ char smem[];
    uint32_t sbase = smem_u32(smem);
    int tid = threadIdx.x, wid = tid >> 5, lane = tid & 31;

    const int GRP = 8;
    int npn = gridDim.x, npm = gridDim.y;
    int pid = blockIdx.y * npn + blockIdx.x;
    int gsz = GRP * npn;
    int gid = pid / gsz;
    int fm = gid * GRP;
    int gm = min(GRP, npm - fm);
    int pid_m = fm + (pid % gsz) % gm;
    int pid_n = (pid % gsz) / gm;
    int m0 = pid_m * 128, n0 = pid_n * 128;

    int warp_m = wid & 3;
    int warp_n = wid >> 2;
    int lrow = lane & 15, lhalf = lane >> 4;

    uint32_t a_off[2], b_off[4];
    #pragma unroll
    for (int i = 0; i < 2; ++i)
        a_off[i] = (uint32_t)((warp_m * 32 + i * 16 + lrow) * SPB + lhalf * 16);
    #pragma unroll
    for (int g = 0; g < 4; ++g)
        b_off[g] = (uint32_t)((warp_n * 64 + g * 16 + lrow) * SPB + lhalf * 16);

    float acc[2][8][4];
    #pragma unroll
    for (int i = 0; i < 2; ++i)
        #pragma unroll
        for (int j = 0; j < 8; ++j)
            #pragma unroll
            for (int t = 0; t < 4; ++t) acc[i][j][t] = 0.f;

    int nch = K >> 5;

    auto issue = [&](int c) {
        if (c < nch) {
            int kc = c << 5;
            uint32_t sb = sbase + (uint32_t)(c % NSTAGE) * STAGE_B;
            #pragma unroll
            for (int u4 = 0; u4 < 4; ++u4) {
                int u = tid + 256 * u4;
                int tile = u >> 9;              // 0=A, 1=B
                int r = (u >> 2) & 127;
                int c16 = u & 3;
                uint32_t dst = sb + (uint32_t)(tile * T_BYTES + r * SPB + c16 * 16);
                if (tile == 0) {
                    int sz = (m0 + r < M) ? 16 : 0;
                    cp_async16(dst, Ah + (size_t)(m0 + r) * lda + kc + c16 * 8, sz);
                } else {
                    cp_async16(dst, Bh + (size_t)(n0 + r) * ldb + kc + c16 * 8, 16);
                }
            }
        }
        cp_commit();
    };

    issue(0); issue(1); issue(2);

    for (int c = 0; c < nch; ++c) {
        cp_wait2();
        __syncthreads();
        issue(c + 3);
        uint32_t sb = sbase + (uint32_t)(c % NSTAGE) * STAGE_B;
        #pragma unroll
        for (int k16 = 0; k16 < 2; ++k16) {
            uint32_t koff = (uint32_t)(k16 * 32);
            uint32_t ah[2][4], bh[4][4];
            #pragma unroll
            for (int i = 0; i < 2; ++i)
                ldsm4(ah[i], sb + 0 * T_BYTES + a_off[i] + koff);
            #pragma unroll
            for (int g = 0; g < 4; ++g)
                ldsm4(bh[g], sb + 1 * T_BYTES + b_off[g] + koff);
            #pragma unroll
            for (int i = 0; i < 2; ++i)
                #pragma unroll
                for (int j = 0; j < 8; ++j) {
                    int g = j >> 1, sI = j & 1;
                    mma_f16(acc[i][j], ah[i], bh[g][sI], bh[g][sI + 2]);
                }
        }
    }

    int trow = lane >> 2, tc2 = (lane & 3) * 2;
    #pragma unroll
    for (int i = 0; i < 2; ++i) {
        #pragma unroll
        for (int half = 0; half < 2; ++half) {
            int m = m0 + warp_m * 32 + i * 16 + half * 8 + trow;
            if (m >= M) continue;
            #pragma unroll
            for (int j = 0; j < 8; ++j) {
                int n = n0 + warp_n * 64 + j * 8 + tc2;
                float vx = acc[i][j][half * 2 + 0];
                float vy = acc[i][j][half * 2 + 1];
                if (bias) { vx += bias[n]; vy += bias[n + 1]; }
                if (n >= gelu_n0) {
                    vx = gelu_f(vx); vy = gelu_f(vy);
                    int cc = HIDDEN + n - gelu_n0;
                    *reinterpret_cast<uint32_t*>(Gh + (size_t)m * CCW + cc) =
                        pack2h(vx, vy);
                } else {
                    *reinterpret_cast<float2*>(C + (size_t)m * ldc + n) =
                        make_float2(vx, vy);
                }
            }
        }
    }
}

// ================= flash attention for block 1 =============================
#define BK 64
#define FSTR 272                       // 128*2 + 16 pad
#define FQ_PLANE (128 * FSTR)          // 34816
#define FK_PLANE (BK * FSTR)           // 17408
#define FS_OFF   FQ_PLANE              // 34816
#define FSTAGE   (2 * FK_PLANE)        // 34816 (K + V)
#define FNS      3
#define FLASH_SMEM (FS_OFF + FNS * FSTAGE)  // 139264
#define NKT (LX / BK)                  // 68

__global__ void __launch_bounds__(256, 1) flash1(
    const f16* __restrict__ Qh,
    const f16* __restrict__ Kh, const f16* __restrict__ Vh,
    f16* __restrict__ Och)
{
    extern __shared__ char smem[];
    uint32_t sbase = smem_u32(smem);
    int tid = threadIdx.x, wid = tid >> 5, lane = tid & 31;
    int head = blockIdx.y;
    int q0 = blockIdx.x * 128;
    size_t hb = (size_t)head * LX * HDIM;
    const f16* qp0 = Qh + hb + (size_t)q0 * HDIM;
    const f16* kp[2] = { Kh + hb, Vh + hb };

    #pragma unroll
    for (int u8 = 0; u8 < 8; ++u8) {
        int u = tid + 256 * u8;
        int r = (u >> 4) & 127, c = u & 15;
        cp_async16(sbase + (uint32_t)(r * FSTR + c * 16),
                   qp0 + (size_t)r * HDIM + c * 8, 16);
    }
    cp_commit();

    auto issueKV = [&](int it) {
        if (it < NKT) {
            int kv0 = it * BK;
            #pragma unroll
            for (int u8 = 0; u8 < 8; ++u8) {
                int u = tid + 256 * u8;
                int pl = u >> 10, r = (u >> 4) & 63, c = u & 15;
                cp_async16(sbase + (uint32_t)(FS_OFF + (it % FNS) * FSTAGE +
                                              pl * FK_PLANE + r * FSTR + c * 16),
                           kp[pl] + (size_t)(kv0 + r) * HDIM + c * 8, 16);
            }
        }
        cp_commit();
    };
    issueKV(0);
    issueKV(1);

    uint32_t a_addr = sbase + (uint32_t)((wid * 16 + (lane & 15)) * FSTR +
                                         (lane >> 4) * 16);
    uint32_t bk_rel = (uint32_t)((lane & 15) * FSTR + (lane >> 4) * 16);
    uint32_t bv_rel = (uint32_t)(((((lane >> 3) & 1) * 8) + (lane & 7)) * FSTR +
                                 ((lane >> 4) & 1) * 16);

    float accO[16][4];
    #pragma unroll
    for (int j = 0; j < 16; ++j)
        #pragma unroll
        for (int t = 0; t < 4; ++t) accO[j][t] = 0.f;
    float mrow0 = -1e30f, mrow1 = -1e30f, lsum0 = 0.f, lsum1 = 0.f;
    const float scl = 0.08838834764831845f;

    for (int it = 0; it < NKT; ++it) {
        cp_wait1();
        __syncthreads();
        issueKV(it + 2);
        uint32_t kb = sbase + FS_OFF + (uint32_t)(it % FNS) * FSTAGE;

        float s[8][4];
        #pragma unroll
        for (int j = 0; j < 8; ++j)
            #pragma unroll
            for (int t = 0; t < 4; ++t) s[j][t] = 0.f;
        #pragma unroll
        for (int ks = 0; ks < 8; ++ks) {
            uint32_t aqh[4];
            ldsm4(aqh, a_addr + ks * 32);
            uint32_t bh[4][4];
            #pragma unroll
            for (int g = 0; g < 4; ++g)
                ldsm4(bh[g], kb + bk_rel + g * (16 * FSTR) + ks * 32);
            #pragma unroll
            for (int j = 0; j < 8; ++j)
                mma_f16(s[j], aqh, bh[j >> 1][j & 1], bh[j >> 1][(j & 1) + 2]);
        }

        float m0 = -1e30f, m1 = -1e30f;
        #pragma unroll
        for (int j = 0; j < 8; ++j) {
            s[j][0] *= scl; s[j][1] *= scl; s[j][2] *= scl; s[j][3] *= scl;
            m0 = fmaxf(m0, fmaxf(s[j][0], s[j][1]));
            m1 = fmaxf(m1, fmaxf(s[j][2], s[j][3]));
        }
        m0 = fmaxf(m0, __shfl_xor_sync(0xffffffffu, m0, 1));
        m0 = fmaxf(m0, __shfl_xor_sync(0xffffffffu, m0, 2));
        m1 = fmaxf(m1, __shfl_xor_sync(0xffffffffu, m1, 1));
        m1 = fmaxf(m1, __shfl_xor_sync(0xffffffffu, m1, 2));
        float mn0 = fmaxf(mrow0, m0), mn1 = fmaxf(mrow1, m1);
        float al0 = __expf(mrow0 - mn0), al1 = __expf(mrow1 - mn1);
        mrow0 = mn0; mrow1 = mn1;

        uint32_t ph[8][2];
        float ps0 = 0.f, ps1 = 0.f;
        #pragma unroll
        for (int j = 0; j < 8; ++j) {
            float p00 = __expf(s[j][0] - mn0), p01 = __expf(s[j][1] - mn0);
            float p10 = __expf(s[j][2] - mn1), p11 = __expf(s[j][3] - mn1);
            ps0 += p00 + p01; ps1 += p10 + p11;
            ph[j][0] = pack2h(p00, p01);
            ph[j][1] = pack2h(p10, p11);
        }
        lsum0 = lsum0 * al0 + ps0;
        lsum1 = lsum1 * al1 + ps1;
        #pragma unroll
        for (int j = 0; j < 16; ++j) {
            accO[j][0] *= al0; accO[j][1] *= al0;
            accO[j][2] *= al1; accO[j][3] *= al1;
        }

        uint32_t vb = kb + FK_PLANE;
        #pragma unroll
        for (int s4 = 0; s4 < 4; ++s4) {
            uint32_t Ahf[4] = { ph[2 * s4][0], ph[2 * s4][1],
                                ph[2 * s4 + 1][0], ph[2 * s4 + 1][1] };
            #pragma unroll
            for (int g = 0; g < 8; ++g) {
                uint32_t bvh[4];
                ldsm4t(bvh, vb + bv_rel + s4 * (16 * FSTR) + g * 32);
                mma_f16(accO[2 * g],     Ahf, bvh[0], bvh[1]);
                mma_f16(accO[2 * g + 1], Ahf, bvh[2], bvh[3]);
            }
        }
    }

    lsum0 += __shfl_xor_sync(0xffffffffu, lsum0, 1);
    lsum0 += __shfl_xor_sync(0xffffffffu, lsum0, 2);
    lsum1 += __shfl_xor_sync(0xffffffffu, lsum1, 1);
    lsum1 += __shfl_xor_sync(0xffffffffu, lsum1, 2);
    float inv0 = 1.f / lsum0, inv1 = 1.f / lsum1;
    int r0 = q0 + wid * 16 + (lane >> 2);
    int cbase = head * HDIM + (lane & 3) * 2;
    #pragma unroll
    for (int j = 0; j < 16; ++j) {
        int c = cbase + j * 8;
        *reinterpret_cast<uint32_t*>(Och + (size_t)r0 * CCW + c) =
            pack2h(accO[j][0] * inv0, accO[j][1] * inv0);
        *reinterpret_cast<uint32_t*>(Och + (size_t)(r0 + 8) * CCW + c) =
            pack2h(accO[j][2] * inv1, accO[j][3] * inv1);
    }
}

// ---------------- SIMT GEMM (block-2 QK^T only) ----------------------------
__global__ void __launch_bounds__(256) sgemm_abt(
    const float* __restrict__ A, int lda, long long sA,
    const float* __restrict__ B, int ldb, long long sB,
    float* __restrict__ C, int ldc, long long sC,
    int M, int N, int K, float alpha)
{
    __shared__ float As[8][128];
    __shared__ float Bs[8][128];
    int bz = blockIdx.z;
    A += (size_t)sA * bz;
    B += (size_t)sB * bz;
    C += (size_t)sC * bz;
    int m0 = blockIdx.y * 128;
    int n0 = blockIdx.x * 128;
    int tid = threadIdx.x;
    int tx = tid & 15, ty = tid >> 4;
    int lrow = tid >> 1;
    int lcol = (tid & 1) * 4;

    float acc[8][8];
    #pragma unroll
    for (int i = 0; i < 8; i++)
        #pragma unroll
        for (int j = 0; j < 8; j++) acc[i][j] = 0.f;

    for (int k0 = 0; k0 < K; k0 += 8) {
        float4 av = make_float4(0.f, 0.f, 0.f, 0.f);
        float4 bv = make_float4(0.f, 0.f, 0.f, 0.f);
        if (m0 + lrow < M && k0 + lcol < K)
            av = *reinterpret_cast<const float4*>(A + (size_t)(m0 + lrow) * lda + k0 + lcol);
        if (n0 + lrow < N && k0 + lcol < K)
            bv = *reinterpret_cast<const float4*>(B + (size_t)(n0 + lrow) * ldb + k0 + lcol);
        As[lcol + 0][lrow] = av.x; As[lcol + 1][lrow] = av.y;
        As[lcol + 2][lrow] = av.z; As[lcol + 3][lrow] = av.w;
        Bs[lcol + 0][lrow] = bv.x; Bs[lcol + 1][lrow] = bv.y;
        Bs[lcol + 2][lrow] = bv.z; Bs[lcol + 3][lrow] = bv.w;
        __syncthreads();
        #pragma unroll
        for (int k = 0; k < 8; k++) {
            float ra[8], rb[8];
            #pragma unroll
            for (int i = 0; i < 8; i++) ra[i] = As[k][ty + 16 * i];
            #pragma unroll
            for (int j = 0; j < 8; j++) rb[j] = Bs[k][tx + 16 * j];
            #pragma unroll
            for (int i = 0; i < 8; i++)
                #pragma unroll
                for (int j = 0; j < 8; j++)
                    acc[i][j] = fmaf(ra[i], rb[j], acc[i][j]);
        }
        __syncthreads();
    }

    #pragma unroll
    for (int i = 0; i < 8; i++) {
        int m = m0 + ty + 16 * i;
        if (m >= M) continue;
        #pragma unroll
        for (int j = 0; j < 8; j++) {
            int n = n0 + tx + 16 * j;
            if (n >= N) continue;
            C[(size_t)m * ldc + n] = alpha * acc[i][j];
        }
    }
}

// ---------------- block-2 PV: split-K rank-1 updates -----------------------
#define KSPLIT 16
__global__ void __launch_bounds__(256) zero_o2()
{
    int idx = blockIdx.x * 256 + threadIdx.x;
    if (idx < NHEADS * NC * HDIM) g_o2[idx] = 0.f;
}
__global__ void __launch_bounds__(256) pv2_kernel()
{
    int h = blockIdx.y, ks = blockIdx.x;
    int chunk = (LC + KSPLIT - 1) / KSPLIT;
    int k0 = ks * chunk, k1 = min(LC, k0 + chunk);
    int d = threadIdx.x & 127, g = threadIdx.x >> 7;
    const float* S = g_s2 + (size_t)h * NC * LC;
    const float* V = g_v2 + (size_t)h * LC * HDIM;
    float acc[10];
    #pragma unroll
    for (int i = 0; i < 10; ++i) acc[i] = 0.f;
    for (int k = k0; k < k1; ++k) {
        float v = V[(size_t)k * HDIM + d];
        #pragma unroll
        for (int i = 0; i < 10; ++i)
            acc[i] = fmaf(__ldg(S + (size_t)(g * 10 + i) * LC + k), v, acc[i]);
    }
    #pragma unroll
    for (int i = 0; i < 10; ++i)
        atomicAdd(&g_o2[((size_t)h * NC + g * 10 + i) * HDIM + d], acc[i]);
}
__global__ void __launch_bounds__(256) o2_to_cc()
{
    int idx = blockIdx.x * 256 + threadIdx.x;
    if (idx >= NHEADS * NC * HDIM) return;
    int d = idx & 127;
    int i = (idx >> 7) % NC;
    int h = idx / (NC * HDIM);
    g_cch[(size_t)(LX + i) * CCW + h * HDIM + d] = __float2half_rn(g_o2[idx]);
}

// ---------------- convert fp32 -> fp16 -------------------------------------
__global__ void __launch_bounds__(256) convert_h(
    const float4* __restrict__ src, uint2* __restrict__ h, int n4)
{
    int idx = blockIdx.x * 256 + threadIdx.x;
    if (idx >= n4) return;
    float4 v = src[idx];
    uint2 r;
    r.x = pack2h(v.x, v.y);
    r.y = pack2h(v.z, v.w);
    h[idx] = r;
}

// ---------------- modulation: m = silu(vec) @ mod_w^T + mod_b --------------
__global__ void __launch_bounds__(256) mod_kernel(
    const float* __restrict__ vec, const float* __restrict__ mod_w,
    const float* __restrict__ mod_b)
{
    __shared__ float sv[HIDDEN];
    for (int i = threadIdx.x; i < HIDDEN; i += 256) {
        float xv = vec[i];
        sv[i] = xv / (1.f + __expf(-xv));
    }
    __syncthreads();
    int n = blockIdx.x * 8 + (threadIdx.x >> 5);
    int lane = threadIdx.x & 31;
    const float4* w4 = reinterpret_cast<const float4*>(mod_w + (size_t)n * HIDDEN);
    float acc = 0.f;
    #pragma unroll
    for (int i = 0; i < 12; ++i) {
        float4 w = w4[lane + 32 * i];
        int k = (lane + 32 * i) * 4;
        acc += w.x * sv[k] + w.y * sv[k + 1] + w.z * sv[k + 2] + w.w * sv[k + 3];
    }
    acc = warp_sum(acc);
    if (lane == 0) g_mod[n] = acc + mod_b[n];
}

// ---------------- layernorm + modulate -> fp16 (float4) ---------------------
__global__ void __launch_bounds__(128) ln_mod_kernel(
    const float* __restrict__ x, const float* __restrict__ concepts)
{
    __shared__ float sbuf[4];
    int row = blockIdx.x;
    const float4* src = (row < LX)
        ? reinterpret_cast<const float4*>(x + (size_t)row * HIDDEN)
        : reinterpret_cast<const float4*>(concepts + (size_t)(row - LX) * HIDDEN);
    int tid = threadIdx.x;
    float4 v[3];
    float s = 0.f;
    #pragma unroll
    for (int i = 0; i < 3; i++) {
        v[i] = src[tid + 128 * i];
        s += v[i].x + v[i].y + v[i].z + v[i].w;
    }
    s = block_sum<128>(s, sbuf);
    float mu = s * (1.0f / 1536.0f);
    float s2 = 0.f;
    #pragma unroll
    for (int i = 0; i < 3; i++) {
        float dx = v[i].x - mu, dy = v[i].y - mu, dz = v[i].z - mu, dw = v[i].w - mu;
        s2 = fmaf(dx, dx, s2); s2 = fmaf(dy, dy, s2);
        s2 = fmaf(dz, dz, s2); s2 = fmaf(dw, dw, s2);
    }
    s2 = block_sum<128>(s2, sbuf);
    float rstd = rsqrtf(s2 * (1.0f / 1536.0f) + 1e-6f);
    #pragma unroll
    for (int i = 0; i < 3; i++) {
        int j4 = tid + 128 * i;
        float4 sc = *reinterpret_cast<const float4*>(g_mod + HIDDEN + j4 * 4);
        float4 sh = *reinterpret_cast<const float4*>(g_mod + j4 * 4);
        float ox = (1.f + sc.x) * ((v[i].x - mu) * rstd) + sh.x;
        float oy = (1.f + sc.y) * ((v[i].y - mu) * rstd) + sh.y;
        float oz = (1.f + sc.z) * ((v[i].z - mu) * rstd) + sh.z;
        float ow = (1.f + sc.w) * ((v[i].w - mu) * rstd) + sh.w;
        uint2 r;
        r.x = pack2h(ox, oy);
        r.y = pack2h(oz, ow);
        *reinterpret_cast<uint2*>(g_xmh + (size_t)row * HIDDEN + j4 * 4) = r;
    }
}

// ---------------- attention prep (warp per token-head, float4) -------------
__device__ __forceinline__ float4 rope4(float4 t, const float* __restrict__ pe,
                                        int tok, int lane)
{
    float4 p0 = *reinterpret_cast<const float4*>(pe + ((size_t)tok * 64 + lane * 2) * 4);
    float4 p1 = *reinterpret_cast<const float4*>(pe + ((size_t)tok * 64 + lane * 2 + 1) * 4);
    float4 r;
    r.x = p0.x * t.x + p0.y * t.y;
    r.y = p0.z * t.x + p0.w * t.y;
    r.z = p1.x * t.z + p1.y * t.w;
    r.w = p1.z * t.z + p1.w * t.w;
    return r;
}

__global__ void __launch_bounds__(384) attn_prep1(
    const float* __restrict__ pe, const float* __restrict__ cpe,
    const float* __restrict__ q_scale, const float* __restrict__ k_scale)
{
    int t = blockIdx.x;
    int h = threadIdx.x >> 5, lane = threadIdx.x & 31;
    const float* hrow = g_h + (size_t)t * QKVW;
    float4 q = *reinterpret_cast<const float4*>(hrow + h * HDIM + lane * 4);
    float4 k = *reinterpret_cast<const float4*>(hrow + HIDDEN + h * HDIM + lane * 4);
    float4 v = *reinterpret_cast<const float4*>(hrow + 2 * HIDDEN + h * HDIM + lane * 4);
    float sq = q.x * q.x + q.y * q.y + q.z * q.z + q.w * q.w;
    float sk = k.x * k.x + k.y * k.y + k.z * k.z + k.w * k.w;
    sq = warp_sum(sq); sk = warp_sum(sk);
    float rq = rsqrtf(sq * (1.f / 128.f) + 1e-6f);
    float rk = rsqrtf(sk * (1.f / 128.f) + 1e-6f);
    float4 qs = *reinterpret_cast<const float4*>(q_scale + lane * 4);
    float4 ks = *reinterpret_cast<const float4*>(k_scale + lane * 4);
    float4 qn = make_float4(q.x * rq * qs.x, q.y * rq * qs.y,
                            q.z * rq * qs.z, q.w * rq * qs.w);
    float4 kn = make_float4(k.x * rk * ks.x, k.y * rk * ks.y,
                            k.z * rk * ks.z, k.w * rk * ks.w);
    float4 qr = rope4(qn, pe, t, lane);
    float4 kr = rope4(kn, pe, t, lane);
    size_t qi = ((size_t)h * LX + t) * HDIM + lane * 4;
    uint2 r;
    r.x = pack2h(qr.x, qr.y); r.y = pack2h(qr.z, qr.w);
    *reinterpret_cast<uint2*>(g_q1h + qi) = r;
    r.x = pack2h(kr.x, kr.y); r.y = pack2h(kr.z, kr.w);
    *reinterpret_cast<uint2*>(g_k1h + qi) = r;
    r.x = pack2h(v.x, v.y); r.y = pack2h(v.z, v.w);
    *reinterpret_cast<uint2*>(g_v1h + qi) = r;
    if (t >= TXT) {
        int j = NC + (t - TXT);
        float4 kc = rope4(kn, cpe, j, lane);
        size_t ki = ((size_t)h * LC + j) * HDIM + lane * 4;
        *reinterpret_cast<float4*>(g_k2 + ki) = kc;
        *reinterpret_cast<float4*>(g_v2 + ki) = v;
    }
}

__global__ void __launch_bounds__(384) attn_prep2(
    const float* __restrict__ cpe,
    const float* __restrict__ q_scale, const float* __restrict__ k_scale)
{
    int i = blockIdx.x;
    int h = threadIdx.x >> 5, lane = threadIdx.x & 31;
    const float* hrow = g_h + (size_t)(LX + i) * QKVW;
    float4 q = *reinterpret_cast<const float4*>(hrow + h * HDIM + lane * 4);
    float4 k = *reinterpret_cast<const float4*>(hrow + HIDDEN + h * HDIM + lane * 4);
    float4 v = *reinterpret_cast<const float4*>(hrow + 2 * HIDDEN + h * HDIM + lane * 4);
    float sq = q.x * q.x + q.y * q.y + q.z * q.z + q.w * q.w;
    float sk = k.x * k.x + k.y * k.y + k.z * k.z + k.w * k.w;
    sq = warp_sum(sq); sk = warp_sum(sk);
    float rq = rsqrtf(sq * (1.f / 128.f) + 1e-6f);
    float rk = rsqrtf(sk * (1.f / 128.f) + 1e-6f);
    float4 qs = *reinterpret_cast<const float4*>(q_scale + lane * 4);
    float4 ks = *reinterpret_cast<const float4*>(k_scale + lane * 4);
    float4 qn = make_float4(q.x * rq * qs.x, q.y * rq * qs.y,
                            q.z * rq * qs.z, q.w * rq * qs.w);
    float4 kn = make_float4(k.x * rk * ks.x, k.y * rk * ks.y,
                            k.z * rk * ks.z, k.w * rk * ks.w);
    float4 qr = rope4(qn, cpe, i, lane);
    float4 kr = rope4(kn, cpe, i, lane);
    *reinterpret_cast<float4*>(g_q2 + ((size_t)h * NC + i) * HDIM + lane * 4) = qr;
    size_t ki = ((size_t)h * LC + i) * HDIM + lane * 4;
    *reinterpret_cast<float4*>(g_k2 + ki) = kr;
    *reinterpret_cast<float4*>(g_v2 + ki) = v;
}

// ---------------- row softmax (block-2 path) -------------------------------
__global__ void __launch_bounds__(256) softmax_rows(float* __restrict__ S, int ncol)
{
    __shared__ float sbuf[8];
    float* row = S + (size_t)blockIdx.x * ncol;
    int tid = threadIdx.x;
    float v[17];
    float mx = -1e30f;
    #pragma unroll
    for (int i = 0; i < 17; i++) {
        int c = tid + 256 * i;
        v[i] = (c < ncol) ? row[c] : -1e30f;
        mx = fmaxf(mx, v[i]);
    }
    mx = block_max<256>(mx, sbuf);
    float s = 0.f;
    #pragma unroll
    for (int i = 0; i < 17; i++) { v[i] = __expf(v[i] - mx); s += v[i]; }
    s = block_sum<256>(s, sbuf);
    float inv = 1.f / s;
    #pragma unroll
    for (int i = 0; i < 17; i++) {
        int c = tid + 256 * i;
        if (c < ncol) row[c] = v[i] * inv;
    }
}

// ---------------- residual: out = base + gate*(p0 + p1 + b2) (float4) ------
__global__ void __launch_bounds__(256) final_kernel(
    const float* __restrict__ x, const float* __restrict__ concepts,
    const float* __restrict__ b2, float* __restrict__ out)
{
    int idx = blockIdx.x * 256 + threadIdx.x;      // float4 index
    if (idx >= NROWS * (HIDDEN / 4)) return;
    int c4 = idx % (HIDDEN / 4);
    int r = idx / (HIDDEN / 4);
    float4 base = (r < LX)
        ? reinterpret_cast<const float4*>(x)[idx]
        : reinterpret_cast<const float4*>(concepts)[idx - LX * (HIDDEN / 4)];
    float4 g = *reinterpret_cast<const float4*>(g_mod + 2 * HIDDEN + c4 * 4);
    float4 bb = reinterpret_cast<const float4*>(b2)[c4];
    float4 p0 = reinterpret_cast<const float4*>(g_out)[idx];
    float4 p1 = reinterpret_cast<const float4*>(g_out)[idx + NROWS * (HIDDEN / 4)];
    float4 rv;
    rv.x = fmaf(g.x, p0.x + p1.x + bb.x, base.x);
    rv.y = fmaf(g.y, p0.y + p1.y + bb.y, base.y);
    rv.z = fmaf(g.z, p0.z + p1.z + bb.z, base.z);
    rv.w = fmaf(g.w, p0.w + p1.w + bb.w, base.w);
    reinterpret_cast<float4*>(out)[idx] = rv;
}

// ---------------------------------------------------------------------------
extern "C" void kernel_launch(void* const* d_in, const int* in_sizes, int n_in,
                              void* d_out, int out_size)
{
    const float* x        = (const float*)d_in[0];
    const float* concepts = (const float*)d_in[1];
    const float* vec      = (const float*)d_in[2];
    const float* pe       = (const float*)d_in[3];
    const float* cpe      = (const float*)d_in[4];
    const float* w1       = (const float*)d_in[5];
    const float* b1       = (const float*)d_in[6];
    const float* w2       = (const float*)d_in[7];
    const float* b2       = (const float*)d_in[8];
    const float* q_scale  = (const float*)d_in[9];
    const float* k_scale  = (const float*)d_in[10];
    const float* mod_w    = (const float*)d_in[11];
    const float* mod_b    = (const float*)d_in[12];
    float* out = (float*)d_out;

    void* p;
    cudaGetSymbolAddress(&p, g_xmh);  f16* xmh = (f16*)p;
    cudaGetSymbolAddress(&p, g_w1h);  f16* w1h = (f16*)p;
    cudaGetSymbolAddress(&p, g_w2h);  f16* w2h = (f16*)p;
    cudaGetSymbolAddress(&p, g_h);    float* hbuf = (float*)p;
    cudaGetSymbolAddress(&p, g_q1h);  f16* q1h = (f16*)p;
    cudaGetSymbolAddress(&p, g_k1h);  f16* k1h = (f16*)p;
    cudaGetSymbolAddress(&p, g_v1h);  f16* v1h = (f16*)p;
    cudaGetSymbolAddress(&p, g_q2);   float* q2b  = (float*)p;
    cudaGetSymbolAddress(&p, g_k2);   float* k2b  = (float*)p;
    cudaGetSymbolAddress(&p, g_s2);   float* s2b  = (float*)p;
    cudaGetSymbolAddress(&p, g_cch);  f16* cch = (f16*)p;
    cudaGetSymbolAddress(&p, g_out);  float* outb = (float*)p;

    static cudaStream_t s1 = nullptr, s2 = nullptr;
    static cudaEvent_t evFork = nullptr, evW1 = nullptr, evW2 = nullptr,
                       evLN = nullptr, evPrep = nullptr, evB2 = nullptr,
                       evMlp2 = nullptr;
    if (s1 == nullptr) {
        cudaStreamCreateWithFlags(&s1, cudaStreamNonBlocking);
        cudaStreamCreateWithFlags(&s2, cudaStreamNonBlocking);
        cudaEventCreateWithFlags(&evFork, cudaEventDisableTiming);
        cudaEventCreateWithFlags(&evW1, cudaEventDisableTiming);
        cudaEventCreateWithFlags(&evW2, cudaEventDisableTiming);
        cudaEventCreateWithFlags(&evLN, cudaEventDisableTiming);
        cudaEventCreateWithFlags(&evPrep, cudaEventDisableTiming);
        cudaEventCreateWithFlags(&evB2, cudaEventDisableTiming);
        cudaEventCreateWithFlags(&evMlp2, cudaEventDisableTiming);
        cudaFuncSetAttribute(gemm_f16,
                             cudaFuncAttributeMaxDynamicSharedMemorySize, HG_SMEM);
        cudaFuncSetAttribute(flash1,
                             cudaFuncAttributeMaxDynamicSharedMemorySize, FLASH_SMEM);
    }

    const float scl = 0.08838834764831845f;  // 1/sqrt(128)

    // fork: side stream s1 converts weights (full w1 before evW1 — R14 order)
    cudaEventRecord(evFork, 0);
    cudaStreamWaitEvent(s1, evFork, 0);
    cudaStreamWaitEvent(s2, evFork, 0);
    {
        int n4 = (W1OUT * HIDDEN) / 4;
        convert_h<<<(n4 + 255) / 256, 256, 0, s1>>>(
            (const float4*)w1, (uint2*)w1h, n4);
    }
    cudaEventRecord(evW1, s1);
    {
        int n4 = (HIDDEN * CCW) / 4;
        convert_h<<<(n4 + 255) / 256, 256, 0, s1>>>(
            (const float4*)w2, (uint2*)w2h, n4);
    }
    cudaEventRecord(evW2, s1);
    // s2: zero block-2 accumulator early (tiny)
    zero_o2<<<(NHEADS * NC * HDIM + 255) / 256, 256, 0, s2>>>();

    // main: modulation + layernorm
    mod_kernel<<<(3 * HIDDEN) / 8, 256>>>(vec, mod_w, mod_b);
    ln_mod_kernel<<<NROWS, 128>>>(x, concepts);
    cudaEventRecord(evLN, 0);

    // join w1, then qkv half of GEMM1 on main
    cudaStreamWaitEvent(0, evW1, 0);
    gemm_f16<<<dim3(QKVW / 128, (NROWS + 127) / 128), 256, HG_SMEM>>>(
        xmh, HIDDEN, w1h, HIDDEN,
        hbuf, QKVW, nullptr, QKVW,
        NROWS, QKVW, HIDDEN, b1);

    // s1: mlp half of GEMM1 (overlaps prep + flash)
    cudaStreamWaitEvent(s1, evLN, 0);
    gemm_f16<<<dim3(MLPH / 128, (NROWS + 127) / 128), 256, HG_SMEM, s1>>>(
        xmh, HIDDEN, w1h + (size_t)QKVW * HIDDEN, HIDDEN,
        nullptr, 0, cch, 0,
        NROWS, MLPH, HIDDEN, b1 + QKVW);

    // s1: GEMM2 over the MLP K-range; overlaps flash on main.
    gemm_f16<<<dim3(HIDDEN / 128, (NROWS + 127) / 128), 256, HG_SMEM, s1>>>(
        cch + HIDDEN, CCW, w2h + HIDDEN, CCW,
        outb, HIDDEN, nullptr, HIDDEN,
        NROWS, HIDDEN, MLPH, nullptr);
    cudaEventRecord(evMlp2, s1);

    // main: prep (warp-per-row) then flash
    attn_prep1<<<LX, 384>>>(pe, cpe, q_scale, k_scale);
    attn_prep2<<<NC, 384>>>(cpe, q_scale, k_scale);
    cudaEventRecord(evPrep, 0);

    // s2: block-2 chain — concurrent with GEMM2_mlp (s1) and flash (main)
    cudaStreamWaitEvent(s2, evPrep, 0);
    sgemm_abt<<<dim3((LC + 127) / 128, 1, NHEADS), 256, 0, s2>>>(
        q2b, HDIM, (long long)NC * HDIM, k2b, HDIM, (long long)LC * HDIM,
        s2b, LC, (long long)NC * LC, NC, LC, HDIM, scl);
    softmax_rows<<<NHEADS * NC, 256, 0, s2>>>(s2b, LC);
    pv2_kernel<<<dim3(KSPLIT, NHEADS), 256, 0, s2>>>();
    o2_to_cc<<<(NHEADS * NC * HDIM + 255) / 256, 256, 0, s2>>>();
    cudaEventRecord(evB2, s2);

    // main: flash attention
    flash1<<<dim3(LX / 128, NHEADS), 256, FLASH_SMEM>>>(q1h, k1h, v1h, cch);

    // join block-2 (cc rows LX..) and w2 conversion, then GEMM2 attn K-range
    cudaStreamWaitEvent(0, evB2, 0);
    cudaStreamWaitEvent(0, evW2, 0);
    gemm_f16<<<dim3(HIDDEN / 128, (NROWS + 127) / 128), 256, HG_SMEM>>>(
        cch, CCW, w2h, CCW,
        outb + (size_t)NROWS * HIDDEN, HIDDEN, nullptr, HIDDEN,
        NROWS, HIDDEN, HIDDEN, nullptr);
    // final needs GEMM2_mlp part-0 as well
    cudaStreamWaitEvent(0, evMlp2, 0);
    final_kernel<<<(NROWS * (HIDDEN / 4) + 255) / 256, 256>>>(
        x, concepts, b2, out);
}